// round 9
// baseline (speedup 1.0000x reference)
#include <cuda_runtime.h>
#include <cuda_bf16.h>
#include <math.h>

// ---------------------------------------------------------------------------
// N=90000, D=H=128, 2H=256, E=1.44M, G=3000, P=675000.
// ---------------------------------------------------------------------------
#define MAXN 90112
#define MAXG 4096

__device__ float g_agg [MAXN * 128];
__device__ float g_ht  [MAXN * 512];
__device__ float g_h1  [MAXN * 128];
__device__ float g_h2  [MAXN * 128];
__device__ float g_mean[MAXN * 128];
__device__ float g_ls  [MAXN * 128];
__device__ float g_u   [MAXN];
__device__ float g_v   [MAXN];
__device__ float g_colsum[512];
__device__ float g_colsq [512];
__device__ float g_scale [512];
__device__ float g_shift [512];
__device__ float g_pool[MAXG];
__device__ float g_cnt [MAXG];
__device__ float g_acc [2];

// ---------------------------------------------------------------------------
// bf16 helpers: hi/lo split words (two k-adjacent bf16 packed per uint32).
// ---------------------------------------------------------------------------
__device__ __forceinline__ void bfsplit2(float e0, float e1,
                                         unsigned& wh, unsigned& wl) {
    __nv_bfloat16 h0 = __float2bfloat16_rn(e0);
    __nv_bfloat16 h1 = __float2bfloat16_rn(e1);
    __nv_bfloat16 l0 = __float2bfloat16_rn(e0 - __bfloat162float(h0));
    __nv_bfloat16 l1 = __float2bfloat16_rn(e1 - __bfloat162float(h1));
    __nv_bfloat162 vh = __nv_bfloat162(h0, h1);
    __nv_bfloat162 vl = __nv_bfloat162(l0, l1);
    wh = *(unsigned*)&vh;
    wl = *(unsigned*)&vl;
}

__device__ __forceinline__ void mma_bf16(float4& d, const unsigned* a,
                                         unsigned b0, unsigned b1) {
    asm volatile(
        "mma.sync.aligned.m16n8k16.row.col.f32.bf16.bf16.f32 "
        "{%0,%1,%2,%3},{%4,%5,%6,%7},{%8,%9},{%0,%1,%2,%3};"
        : "+f"(d.x), "+f"(d.y), "+f"(d.z), "+f"(d.w)
        : "r"(a[0]), "r"(a[1]), "r"(a[2]), "r"(a[3]), "r"(b0), "r"(b1));
}

// ---------------------------------------------------------------------------
// Edge scatter: agg[dst] += x[src].  One warp per edge, vector red.
// ---------------------------------------------------------------------------
__global__ void scatter_k(const float* __restrict__ X,
                          const int* __restrict__ ei, int E) {
    int gw   = (blockIdx.x * blockDim.x + threadIdx.x) >> 5;
    int lane = threadIdx.x & 31;
    if (gw >= E) return;
    int s = __ldg(ei + gw);
    int d = __ldg(ei + E + gw);
    float4 vv = *(const float4*)(X + (size_t)s * 128 + lane * 4);
    float* dst = g_agg + (size_t)d * 128 + lane * 4;
    asm volatile("red.global.add.v4.f32 [%0], {%1,%2,%3,%4};"
                 :: "l"(dst), "f"(vv.x), "f"(vv.y), "f"(vv.z), "f"(vv.w)
                 : "memory");
}

// ---------------------------------------------------------------------------
// bf16x3 tensor GEMM, BK=32: 96 MMAs between barrier pairs, 2x load MLP.
// 128x128 tile, 8 warps (4m x 2n), warp 32x64, m16n8k16.
// Smem words [k2][m] / [k2][n], 16 k2-rows, stride 136: conflict-free.
// ---------------------------------------------------------------------------
#define BM 128
#define BN 128
#define BK 32
#define KW 136     // word stride per k2-row

#define MMA3(ACC, AH, AL, BH0, BH1, BL0, BL1)  \
    do { mma_bf16(ACC, AH, BH0, BH1);          \
         mma_bf16(ACC, AL, BH0, BH1);          \
         mma_bf16(ACC, AH, BL0, BL1); } while (0)

// MMA phase over one BK=32 tile (two k16 substeps). Shared by both kernels.
#define MMA_PHASE(Ah, Al, Bh, Bl)                                           \
    _Pragma("unroll")                                                       \
    for (int s = 0; s < 2; s++) {                                           \
        int r0 = s * 8 + lk, r1 = s * 8 + lk + 4;                           \
        unsigned ah[2][4], al[2][4];                                        \
        _Pragma("unroll")                                                   \
        for (int wm = 0; wm < 2; wm++) {                                    \
            int mr = mBase + wm * 16 + lm;                                  \
            ah[wm][0] = Ah[r0 * KW + mr];                                   \
            ah[wm][1] = Ah[r0 * KW + mr + 8];                               \
            ah[wm][2] = Ah[r1 * KW + mr];                                   \
            ah[wm][3] = Ah[r1 * KW + mr + 8];                               \
            al[wm][0] = Al[r0 * KW + mr];                                   \
            al[wm][1] = Al[r0 * KW + mr + 8];                               \
            al[wm][2] = Al[r1 * KW + mr];                                   \
            al[wm][3] = Al[r1 * KW + mr + 8];                               \
        }                                                                   \
        _Pragma("unroll")                                                   \
        for (int wn = 0; wn < 8; wn++) {                                    \
            int nc = nBase + wn * 8 + lm;                                   \
            unsigned bh0 = Bh[r0 * KW + nc], bh1 = Bh[r1 * KW + nc];        \
            unsigned bl0 = Bl[r0 * KW + nc], bl1 = Bl[r1 * KW + nc];        \
            _Pragma("unroll")                                               \
            for (int wm = 0; wm < 2; wm++)                                  \
                MMA3(acc[wm][wn], ah[wm], al[wm], bh0, bh1, bl0, bl1);      \
        }                                                                   \
    }

// GEMM1: OUT[:, n0:n0+128] = (X+agg) @ W + bias ; fused colsum/colsq stats.
__global__ void __launch_bounds__(256) gemm1_k(
    const float* __restrict__ X, const float* __restrict__ Wa,
    const float* __restrict__ Wb, const float* __restrict__ bias,
    float* __restrict__ OUT, int N, int ldo) {
    __shared__ unsigned Ah[16 * KW], Al[16 * KW];
    __shared__ unsigned Bh[16 * KW], Bl[16 * KW];
    int tid  = threadIdx.x;
    int row0 = blockIdx.y * BM;
    int n0   = blockIdx.x * BN;
    const float* W = (n0 < 256) ? Wa : Wb;
    int nbase = (n0 < 256) ? n0 : (n0 - 256);
    int lane = tid & 31, wid = tid >> 5;
    int lk = lane & 3, lm = lane >> 2;
    int warpM = wid & 3, warpN = wid >> 2;
    int mBase = warpM * 32, nBase = warpN * 64;
    float4 acc[2][8];
    #pragma unroll
    for (int i = 0; i < 2; i++)
        #pragma unroll
        for (int j = 0; j < 8; j++) acc[i][j] = make_float4(0.f,0.f,0.f,0.f);

    for (int kk = 0; kk < 128; kk += BK) {
        #pragma unroll
        for (int h = 0; h < 4; h++) {
            int idx = h * 256 + tid;
            int m  = idx & 127;
            int kq = (idx >> 7) * 4;          // 0..28 step 4
            int rg = row0 + m;
            float4 a = make_float4(0.f,0.f,0.f,0.f);
            if (rg < N) {
                size_t off = (size_t)rg * 128 + kk + kq;
                float4 xv = *(const float4*)(X + off);
                float4 av = *(const float4*)(g_agg + off);
                a.x = xv.x + av.x; a.y = xv.y + av.y;
                a.z = xv.z + av.z; a.w = xv.w + av.w;
            }
            unsigned wh0, wl0, wh1, wl1;
            bfsplit2(a.x, a.y, wh0, wl0);
            bfsplit2(a.z, a.w, wh1, wl1);
            int aw = (kq >> 1) * KW + m;
            Ah[aw] = wh0; Al[aw] = wl0;
            Ah[aw + KW] = wh1; Al[aw + KW] = wl1;
            const float* wp = W + (size_t)(kk + kq) * 256 + nbase + m;
            float b0 = wp[0], b1 = wp[256], b2 = wp[512], b3 = wp[768];
            bfsplit2(b0, b1, wh0, wl0);
            bfsplit2(b2, b3, wh1, wl1);
            Bh[aw] = wh0; Bl[aw] = wl0;
            Bh[aw + KW] = wh1; Bl[aw + KW] = wl1;
        }
        __syncthreads();
        MMA_PHASE(Ah, Al, Bh, Bl)
        __syncthreads();
    }

    // epilogue: bias, store, per-column stats
    float psx[8]={}, psy[8]={}, pqx[8]={}, pqy[8]={};
    #pragma unroll
    for (int wn = 0; wn < 8; wn++) {
        int col = n0 + nBase + wn * 8 + 2 * lk;
        float bx = bias[col], by = bias[col + 1];
        #pragma unroll
        for (int wm = 0; wm < 2; wm++) {
            float4 d = acc[wm][wn];
            int ra = row0 + mBase + wm * 16 + lm;
            int rb = ra + 8;
            float ox = d.x + bx, oy = d.y + by;
            float oz = d.z + bx, ow = d.w + by;
            if (ra < N) {
                *(float2*)(OUT + (size_t)ra * ldo + col) = make_float2(ox, oy);
                psx[wn] += ox; psy[wn] += oy;
                pqx[wn] += ox * ox; pqy[wn] += oy * oy;
            }
            if (rb < N) {
                *(float2*)(OUT + (size_t)rb * ldo + col) = make_float2(oz, ow);
                psx[wn] += oz; psy[wn] += ow;
                pqx[wn] += oz * oz; pqy[wn] += ow * ow;
            }
        }
    }
    #pragma unroll
    for (int wn = 0; wn < 8; wn++) {
        #pragma unroll
        for (int o = 4; o <= 16; o <<= 1) {
            psx[wn] += __shfl_xor_sync(0xffffffffu, psx[wn], o);
            psy[wn] += __shfl_xor_sync(0xffffffffu, psy[wn], o);
            pqx[wn] += __shfl_xor_sync(0xffffffffu, pqx[wn], o);
            pqy[wn] += __shfl_xor_sync(0xffffffffu, pqy[wn], o);
        }
    }
    if (lane < 4) {
        #pragma unroll
        for (int wn = 0; wn < 8; wn++) {
            int col = n0 + nBase + wn * 8 + 2 * lane;
            atomicAdd(&g_colsum[col],     psx[wn]);
            atomicAdd(&g_colsum[col + 1], psy[wn]);
            atomicAdd(&g_colsq[col],      pqx[wn]);
            atomicAdd(&g_colsq[col + 1],  pqy[wn]);
        }
    }
}

__global__ void bnfin_k(const float* __restrict__ gamma,
                        const float* __restrict__ beta, int N) {
    int c = blockIdx.x * blockDim.x + threadIdx.x;
    float invN = 1.0f / (float)N;
    float mu  = g_colsum[c] * invN;
    float var = g_colsq[c] * invN - mu * mu;
    float sc  = gamma[c] * rsqrtf(var + 1e-5f);
    g_scale[c] = sc;
    g_shift[c] = beta[c] - mu * sc;
}

// GEMM2: OUT[N,128] = BN(HT[:,koff:+256]) [relu] @ W[256,128] + b2.
// Dual mode: when gridDim.x==2, blockIdx.x==1 uses the alternate set.
__global__ void __launch_bounds__(256) gemm2_k(
    const float* __restrict__ HT, const float* __restrict__ W0,
    const float* __restrict__ bias0, float* __restrict__ OUT0,
    const float* __restrict__ W1, const float* __restrict__ bias1,
    float* __restrict__ OUT1,
    int N, int ldh, int koff0, int koff1, int relu) {
    __shared__ unsigned Ah[16 * KW], Al[16 * KW];
    __shared__ unsigned Bh[16 * KW], Bl[16 * KW];
    int tid  = threadIdx.x;
    int row0 = blockIdx.y * BM;
    int alt  = blockIdx.x;
    const float* W    = alt ? W1 : W0;
    const float* bias = alt ? bias1 : bias0;
    float* OUT        = alt ? OUT1 : OUT0;
    int koff          = alt ? koff1 : koff0;
    int lane = tid & 31, wid = tid >> 5;
    int lk = lane & 3, lm = lane >> 2;
    int warpM = wid & 3, warpN = wid >> 2;
    int mBase = warpM * 32, nBase = warpN * 64;
    float4 acc[2][8];
    #pragma unroll
    for (int i = 0; i < 2; i++)
        #pragma unroll
        for (int j = 0; j < 8; j++) acc[i][j] = make_float4(0.f,0.f,0.f,0.f);

    for (int kk = 0; kk < 256; kk += BK) {
        #pragma unroll
        for (int h = 0; h < 4; h++) {
            int idx = h * 256 + tid;
            int m  = idx & 127;
            int kq = (idx >> 7) * 4;
            int rg = row0 + m;
            float4 a = make_float4(0.f,0.f,0.f,0.f);
            if (rg < N) {
                float4 h4 = *(const float4*)(HT + (size_t)rg * ldh + koff + kk + kq);
                float4 sc4 = *(const float4*)(g_scale + koff + kk + kq);
                float4 sh4 = *(const float4*)(g_shift + koff + kk + kq);
                a.x = h4.x * sc4.x + sh4.x;
                a.y = h4.y * sc4.y + sh4.y;
                a.z = h4.z * sc4.z + sh4.z;
                a.w = h4.w * sc4.w + sh4.w;
                if (relu) {
                    a.x = fmaxf(a.x, 0.f); a.y = fmaxf(a.y, 0.f);
                    a.z = fmaxf(a.z, 0.f); a.w = fmaxf(a.w, 0.f);
                }
            }
            unsigned wh0, wl0, wh1, wl1;
            bfsplit2(a.x, a.y, wh0, wl0);
            bfsplit2(a.z, a.w, wh1, wl1);
            int aw = (kq >> 1) * KW + m;
            Ah[aw] = wh0; Al[aw] = wl0;
            Ah[aw + KW] = wh1; Al[aw + KW] = wl1;
            const float* wp = W + (size_t)(kk + kq) * 128 + m;
            float b0 = wp[0], b1 = wp[128], b2 = wp[256], b3 = wp[384];
            bfsplit2(b0, b1, wh0, wl0);
            bfsplit2(b2, b3, wh1, wl1);
            Bh[aw] = wh0; Bl[aw] = wl0;
            Bh[aw + KW] = wh1; Bl[aw + KW] = wl1;
        }
        __syncthreads();
        MMA_PHASE(Ah, Al, Bh, Bl)
        __syncthreads();
    }

    #pragma unroll
    for (int wn = 0; wn < 8; wn++) {
        int col = nBase + wn * 8 + 2 * lk;
        float bx = bias[col], by = bias[col + 1];
        #pragma unroll
        for (int wm = 0; wm < 2; wm++) {
            float4 d = acc[wm][wn];
            int ra = row0 + mBase + wm * 16 + lm;
            int rb = ra + 8;
            if (ra < N)
                *(float2*)(OUT + (size_t)ra * 128 + col) = make_float2(d.x + bx, d.y + by);
            if (rb < N)
                *(float2*)(OUT + (size_t)rb * 128 + col) = make_float2(d.z + bx, d.w + by);
        }
    }
}

// ---------------------------------------------------------------------------
// z epilogue and small kernels.
// ---------------------------------------------------------------------------
__global__ void z_k(const float* __restrict__ MEAN, const float* __restrict__ LS,
                    const float* __restrict__ NOISE, const int* __restrict__ batch,
                    const float* __restrict__ Wn, const float* __restrict__ Wc,
                    int N) {
    __shared__ float klred[8];
    int lane = threadIdx.x & 31;
    int w    = threadIdx.x >> 5;
    int row  = blockIdx.x * 8 + w;
    float klp = 0.f;
    if (row < N) {
        size_t off = (size_t)row * 128 + lane * 4;
        float4 m4 = *(const float4*)(MEAN + off);
        float4 l4 = *(const float4*)(LS + off);
        float4 n4 = *(const float4*)(NOISE + off);
        float4 e4 = make_float4(expf(l4.x), expf(l4.y), expf(l4.z), expf(l4.w));
        float4 z4 = make_float4(n4.x * e4.x + m4.x, n4.y * e4.y + m4.y,
                                n4.z * e4.z + m4.z, n4.w * e4.w + m4.w);
        float4 wa = *(const float4*)(Wc + lane * 4);
        float4 wb = *(const float4*)(Wc + 128 + lane * 4);
        float4 wn = *(const float4*)(Wn + lane * 4);
        float up = z4.x * wa.x + z4.y * wa.y + z4.z * wa.z + z4.w * wa.w;
        float vp = z4.x * wb.x + z4.y * wb.y + z4.z * wb.z + z4.w * wb.w;
        float sp = z4.x * wn.x + z4.y * wn.y + z4.z * wn.z + z4.w * wn.w;
        klp = (1.f + 2.f * l4.x - m4.x * m4.x - e4.x * e4.x)
            + (1.f + 2.f * l4.y - m4.y * m4.y - e4.y * e4.y)
            + (1.f + 2.f * l4.z - m4.z * m4.z - e4.z * e4.z)
            + (1.f + 2.f * l4.w - m4.w * m4.w - e4.w * e4.w);
        #pragma unroll
        for (int o = 16; o > 0; o >>= 1) {
            up  += __shfl_xor_sync(0xffffffffu, up,  o);
            vp  += __shfl_xor_sync(0xffffffffu, vp,  o);
            sp  += __shfl_xor_sync(0xffffffffu, sp,  o);
            klp += __shfl_xor_sync(0xffffffffu, klp, o);
        }
        if (lane == 0) {
            g_u[row] = up;
            g_v[row] = vp;
            int b = batch[row];
            atomicAdd(&g_pool[b], sp);
            atomicAdd(&g_cnt[b], 1.0f);
        }
    }
    if (lane == 0) klred[w] = (row < N) ? klp : 0.f;
    __syncthreads();
    if (threadIdx.x == 0) {
        float t = 0.f;
        #pragma unroll
        for (int i = 0; i < 8; i++) t += klred[i];
        atomicAdd(&g_acc[0], t);
    }
}

__global__ void num_k(const float* __restrict__ bridge_num,
                      const float* __restrict__ bnp,
                      float* __restrict__ out_np, int G) {
    __shared__ float red[256];
    int g = blockIdx.x * 256 + threadIdx.x;
    float d = 0.f;
    if (g < G) {
        float np = g_pool[g] / g_cnt[g] + bnp[0];
        out_np[g] = np;
        d = fabsf(np - bridge_num[g]);
    }
    red[threadIdx.x] = d;
    __syncthreads();
    for (int s = 128; s > 0; s >>= 1) {
        if (threadIdx.x < s) red[threadIdx.x] += red[threadIdx.x + s];
        __syncthreads();
    }
    if (threadIdx.x == 0) atomicAdd(&g_acc[1], red[0]);
}

__global__ void apred_k(const int* __restrict__ bidx,
                        const float* __restrict__ bcp,
                        float* __restrict__ out, int P) {
    int p = blockIdx.x * 256 + threadIdx.x;
    if (p >= P) return;
    int i = __ldg(bidx + p);
    int j = __ldg(bidx + P + p);
    float logit = g_u[i] + g_v[j] + bcp[0];
    out[p] = 1.0f / (1.0f + expf(-logit));
}

__global__ void fin_k(float* __restrict__ out, int P, int N, int G) {
    out[P]     = 0.5f * g_acc[0] / ((float)N * (float)N);
    out[P + 1] = g_acc[1] / (float)G;
}

// ---------------------------------------------------------------------------
// Launcher
// ---------------------------------------------------------------------------
extern "C" void kernel_launch(void* const* d_in, const int* in_sizes, int n_in,
                              void* d_out, int out_size) {
    const float* x          = (const float*)d_in[0];
    const int*   ei         = (const int*)  d_in[1];
    const int*   batch      = (const int*)  d_in[2];
    const float* bridge_num = (const float*)d_in[3];
    const int*   bidx       = (const int*)  d_in[4];
    const float* noise      = (const float*)d_in[5];
    const float* W1s        = (const float*)d_in[6];
    const float* b1s        = (const float*)d_in[7];
    const float* gammas     = (const float*)d_in[8];
    const float* betas      = (const float*)d_in[9];
    const float* W2s        = (const float*)d_in[10];
    const float* b2s        = (const float*)d_in[11];
    const float* Wn         = (const float*)d_in[12];
    const float* bnp        = (const float*)d_in[13];
    const float* Wc         = (const float*)d_in[14];
    const float* bcp        = (const float*)d_in[15];
    float* out = (float*)d_out;

    int N = in_sizes[0] / 128;
    int E = in_sizes[1] / 2;
    int G = in_sizes[3];
    int P = in_sizes[4] / 2;

    float *agg, *ht, *h1, *h2, *mean, *ls, *colsum, *colsq, *pool, *cnt, *acc;
    cudaGetSymbolAddress((void**)&agg,    g_agg);
    cudaGetSymbolAddress((void**)&ht,     g_ht);
    cudaGetSymbolAddress((void**)&h1,     g_h1);
    cudaGetSymbolAddress((void**)&h2,     g_h2);
    cudaGetSymbolAddress((void**)&mean,   g_mean);
    cudaGetSymbolAddress((void**)&ls,     g_ls);
    cudaGetSymbolAddress((void**)&colsum, g_colsum);
    cudaGetSymbolAddress((void**)&colsq,  g_colsq);
    cudaGetSymbolAddress((void**)&pool,   g_pool);
    cudaGetSymbolAddress((void**)&cnt,    g_cnt);
    cudaGetSymbolAddress((void**)&acc,    g_acc);

    int rb = (N + BM - 1) / BM;
    int scat_blocks = (E * 32 + 511) / 512;

    // ---- layer 0 ----
    cudaMemsetAsync(agg, 0, (size_t)N * 128 * sizeof(float));
    scatter_k<<<scat_blocks, 512>>>(x, ei, E);
    cudaMemsetAsync(colsum, 0, 512 * sizeof(float));
    cudaMemsetAsync(colsq,  0, 512 * sizeof(float));
    gemm1_k<<<dim3(2, rb), 256>>>(x, W1s, W1s, b1s, ht, N, 256);
    bnfin_k<<<1, 256>>>(gammas, betas, N);
    gemm2_k<<<dim3(1, rb), 256>>>(ht, W2s, b2s, h1, W2s, b2s, h1, N, 256, 0, 0, 1);

    // ---- layer 1 ----
    cudaMemsetAsync(agg, 0, (size_t)N * 128 * sizeof(float));
    scatter_k<<<scat_blocks, 512>>>(h1, ei, E);
    cudaMemsetAsync(colsum, 0, 512 * sizeof(float));
    cudaMemsetAsync(colsq,  0, 512 * sizeof(float));
    gemm1_k<<<dim3(2, rb), 256>>>(h1, W1s + 1 * 128 * 256, W1s, b1s + 256, ht, N, 256);
    bnfin_k<<<1, 256>>>(gammas + 256, betas + 256, N);
    gemm2_k<<<dim3(1, rb), 256>>>(ht, W2s + 1 * 256 * 128, b2s + 128, h2,
                                  W2s + 1 * 256 * 128, b2s + 128, h2, N, 256, 0, 0, 1);

    // ---- layers 2+3 combined (shared A = h2 + agg(h2)) ----
    cudaMemsetAsync(agg, 0, (size_t)N * 128 * sizeof(float));
    scatter_k<<<scat_blocks, 512>>>(h2, ei, E);
    cudaMemsetAsync(colsum, 0, 512 * sizeof(float));
    cudaMemsetAsync(colsq,  0, 512 * sizeof(float));
    gemm1_k<<<dim3(4, rb), 256>>>(h2, W1s + 2 * 128 * 256, W1s + 3 * 128 * 256,
                                  b1s + 512, ht, N, 512);
    bnfin_k<<<1, 512>>>(gammas + 512, betas + 512, N);
    gemm2_k<<<dim3(2, rb), 256>>>(ht, W2s + 2 * 256 * 128, b2s + 256, mean,
                                  W2s + 3 * 256 * 128, b2s + 384, ls,
                                  N, 512, 0, 256, 0);

    // ---- epilogue ----
    cudaMemsetAsync(pool, 0, G * sizeof(float));
    cudaMemsetAsync(cnt,  0, G * sizeof(float));
    cudaMemsetAsync(acc,  0, 2 * sizeof(float));
    z_k<<<(N + 7) / 8, 256>>>(mean, ls, noise, batch, Wn, Wc, N);
    num_k<<<(G + 255) / 256, 256>>>(bridge_num, bnp, out + P + 2, G);
    apred_k<<<(P + 255) / 256, 256>>>(bidx, bcp, out, P);
    fin_k<<<1, 1>>>(out, P, N, G);
}

// round 11
// speedup vs baseline: 1.3846x; 1.3846x over previous
#include <cuda_runtime.h>
#include <cuda_bf16.h>
#include <math.h>

// ---------------------------------------------------------------------------
// N=90000, D=H=128, 2H=256, E=1.44M, G=3000, P=675000.
// ---------------------------------------------------------------------------
#define MAXN 90112
#define MAXG 4096

__device__ float g_agg [MAXN * 128];
__device__ float g_ht  [MAXN * 512];
__device__ float g_h1  [MAXN * 128];
__device__ float g_h2  [MAXN * 128];
__device__ float g_mean[MAXN * 128];
__device__ float g_ls  [MAXN * 128];
__device__ float g_u   [MAXN];
__device__ float g_v   [MAXN];
__device__ float g_colsum[512];
__device__ float g_colsq [512];
__device__ float g_scale [512];
__device__ float g_shift [512];
__device__ float g_pool[MAXG];
__device__ float g_cnt [MAXG];
__device__ float g_acc [2];

// ---------------------------------------------------------------------------
// bf16 split + mma helpers.
// ---------------------------------------------------------------------------
__device__ __forceinline__ void bfsplit2(float e0, float e1,
                                         unsigned& wh, unsigned& wl) {
    __nv_bfloat16 h0 = __float2bfloat16_rn(e0);
    __nv_bfloat16 h1 = __float2bfloat16_rn(e1);
    __nv_bfloat16 l0 = __float2bfloat16_rn(e0 - __bfloat162float(h0));
    __nv_bfloat16 l1 = __float2bfloat16_rn(e1 - __bfloat162float(h1));
    __nv_bfloat162 vh = __nv_bfloat162(h0, h1);
    __nv_bfloat162 vl = __nv_bfloat162(l0, l1);
    wh = *(unsigned*)&vh;
    wl = *(unsigned*)&vl;
}

__device__ __forceinline__ void mma_bf16(float4& d, const unsigned* a,
                                         unsigned b0, unsigned b1) {
    asm volatile(
        "mma.sync.aligned.m16n8k16.row.col.f32.bf16.bf16.f32 "
        "{%0,%1,%2,%3},{%4,%5,%6,%7},{%8,%9},{%0,%1,%2,%3};"
        : "+f"(d.x), "+f"(d.y), "+f"(d.z), "+f"(d.w)
        : "r"(a[0]), "r"(a[1]), "r"(a[2]), "r"(a[3]), "r"(b0), "r"(b1));
}

// cp.async helpers (16B, L1-bypass; optional zero-fill via src-size=0)
__device__ __forceinline__ void cp16(void* dst, const void* src) {
    unsigned d = (unsigned)__cvta_generic_to_shared(dst);
    asm volatile("cp.async.cg.shared.global [%0], [%1], 16;" :: "r"(d), "l"(src));
}
__device__ __forceinline__ void cp16z(void* dst, const void* src, bool valid) {
    unsigned d = (unsigned)__cvta_generic_to_shared(dst);
    int sz = valid ? 16 : 0;
    asm volatile("cp.async.cg.shared.global [%0], [%1], 16, %2;"
                 :: "r"(d), "l"(src), "r"(sz));
}
#define CP_COMMIT() asm volatile("cp.async.commit_group;")
#define CP_WAIT0()  asm volatile("cp.async.wait_group 0;")

// ---------------------------------------------------------------------------
// Edge scatter: agg[dst] += x[src].  One warp per edge, vector red.
// ---------------------------------------------------------------------------
__global__ void scatter_k(const float* __restrict__ X,
                          const int* __restrict__ ei, int E) {
    int gw   = (blockIdx.x * blockDim.x + threadIdx.x) >> 5;
    int lane = threadIdx.x & 31;
    if (gw >= E) return;
    int s = __ldg(ei + gw);
    int d = __ldg(ei + E + gw);
    float4 vv = *(const float4*)(X + (size_t)s * 128 + lane * 4);
    float* dst = g_agg + (size_t)d * 128 + lane * 4;
    asm volatile("red.global.add.v4.f32 [%0], {%1,%2,%3,%4};"
                 :: "l"(dst), "f"(vv.x), "f"(vv.y), "f"(vv.z), "f"(vv.w)
                 : "memory");
}

// ---------------------------------------------------------------------------
// bf16x3 GEMM with cp.async staging. BK=16, 128x128 tile, 8 warps (4m x 2n),
// warp 32x64, m16n8k16.  Split operands [k2][m]/[k2][n] stride 136 (words).
// Raw staging: A rows padded to 20 words, B rows to 132 words.
// ---------------------------------------------------------------------------
#define BM 128
#define BN 128
#define BK 16
#define KW 136
#define SAW 20
#define SBW 132

#define MMA3(ACC, AH, AL, BH0, BH1, BL0, BL1)  \
    do { mma_bf16(ACC, AH, BH0, BH1);          \
         mma_bf16(ACC, AL, BH0, BH1);          \
         mma_bf16(ACC, AH, BL0, BL1); } while (0)

// One k16 MMA step over the split operand arrays (R8-proven pattern).
#define MMA_PHASE(Ah, Al, Bh, Bl)                                           \
    {                                                                       \
        unsigned ah[2][4], al[2][4];                                        \
        _Pragma("unroll")                                                   \
        for (int wm = 0; wm < 2; wm++) {                                    \
            int mr = mBase + wm * 16 + lm;                                  \
            ah[wm][0] = Ah[lk * KW + mr];                                   \
            ah[wm][1] = Ah[lk * KW + mr + 8];                               \
            ah[wm][2] = Ah[(lk + 4) * KW + mr];                             \
            ah[wm][3] = Ah[(lk + 4) * KW + mr + 8];                         \
            al[wm][0] = Al[lk * KW + mr];                                   \
            al[wm][1] = Al[lk * KW + mr + 8];                               \
            al[wm][2] = Al[(lk + 4) * KW + mr];                             \
            al[wm][3] = Al[(lk + 4) * KW + mr + 8];                         \
        }                                                                   \
        _Pragma("unroll")                                                   \
        for (int wn = 0; wn < 8; wn++) {                                    \
            int nc = nBase + wn * 8 + lm;                                   \
            unsigned bh0 = Bh[lk * KW + nc], bh1 = Bh[(lk + 4) * KW + nc];  \
            unsigned bl0 = Bl[lk * KW + nc], bl1 = Bl[(lk + 4) * KW + nc];  \
            _Pragma("unroll")                                               \
            for (int wm = 0; wm < 2; wm++)                                  \
                MMA3(acc[wm][wn], ah[wm], al[wm], bh0, bh1, bl0, bl1);      \
        }                                                                   \
    }

// GEMM1: OUT[:, n0:n0+128] = (X+agg) @ W + bias ; fused colsum/colsq stats.
__global__ void __launch_bounds__(256) gemm1_k(
    const float* __restrict__ X, const float* __restrict__ Wa,
    const float* __restrict__ Wb, const float* __restrict__ bias,
    float* __restrict__ OUT, int N, int ldo) {
    __shared__ unsigned Ah[8 * KW], Al[8 * KW], Bh[8 * KW], Bl[8 * KW];
    __shared__ float SaX[128 * SAW], SaG[128 * SAW], Sb[16 * SBW];
    int tid  = threadIdx.x;
    int row0 = blockIdx.y * BM;
    int n0   = blockIdx.x * BN;
    const float* W = (n0 < 256) ? Wa : Wb;
    int nbase = (n0 < 256) ? n0 : (n0 - 256);
    int lane = tid & 31, wid = tid >> 5;
    int lk = lane & 3, lm = lane >> 2;
    int warpM = wid & 3, warpN = wid >> 2;
    int mBase = warpM * 32, nBase = warpN * 64;
    float4 acc[2][8];
    #pragma unroll
    for (int i = 0; i < 2; i++)
        #pragma unroll
        for (int j = 0; j < 8; j++) acc[i][j] = make_float4(0.f,0.f,0.f,0.f);

    // issue staging for tile at kk
    auto issue = [&](int kk) {
        #pragma unroll
        for (int h = 0; h < 2; h++) {
            int c = h * 256 + tid;
            int m = c >> 2, kq = (c & 3) * 4;
            int rg = row0 + m;
            bool v = rg < N;
            size_t off = (size_t)(v ? rg : 0) * 128 + kk + kq;
            cp16z(SaX + m * SAW + kq, X + off, v);
            cp16z(SaG + m * SAW + kq, g_agg + off, v);
            int k = c >> 5, nq = (c & 31) * 4;
            cp16(Sb + k * SBW + nq, W + (size_t)(kk + k) * 256 + nbase + nq);
        }
        CP_COMMIT();
    };
    issue(0);

    for (int kk = 0; kk < 128; kk += BK) {
        CP_WAIT0();
        __syncthreads();
        #pragma unroll
        for (int h = 0; h < 2; h++) {
            int idx = h * 256 + tid;
            int m  = idx & 127;
            int kq = (idx >> 7) * 4;
            float4 xv = *(float4*)(SaX + m * SAW + kq);
            float4 av = *(float4*)(SaG + m * SAW + kq);
            float4 a = make_float4(xv.x + av.x, xv.y + av.y,
                                   xv.z + av.z, xv.w + av.w);
            unsigned wh0, wl0, wh1, wl1;
            bfsplit2(a.x, a.y, wh0, wl0);
            bfsplit2(a.z, a.w, wh1, wl1);
            int aw = (kq >> 1) * KW + m;
            Ah[aw] = wh0; Al[aw] = wl0;
            Ah[aw + KW] = wh1; Al[aw + KW] = wl1;
            float b0 = Sb[(kq + 0) * SBW + m];
            float b1 = Sb[(kq + 1) * SBW + m];
            float b2 = Sb[(kq + 2) * SBW + m];
            float b3 = Sb[(kq + 3) * SBW + m];
            bfsplit2(b0, b1, wh0, wl0);
            bfsplit2(b2, b3, wh1, wl1);
            Bh[aw] = wh0; Bl[aw] = wl0;
            Bh[aw + KW] = wh1; Bl[aw + KW] = wl1;
        }
        __syncthreads();
        if (kk + BK < 128) issue(kk + BK);
        MMA_PHASE(Ah, Al, Bh, Bl)
    }

    // epilogue: bias, store, per-column stats
    float psx[8]={}, psy[8]={}, pqx[8]={}, pqy[8]={};
    #pragma unroll
    for (int wn = 0; wn < 8; wn++) {
        int col = n0 + nBase + wn * 8 + 2 * lk;
        float bx = bias[col], by = bias[col + 1];
        #pragma unroll
        for (int wm = 0; wm < 2; wm++) {
            float4 d = acc[wm][wn];
            int ra = row0 + mBase + wm * 16 + lm;
            int rb = ra + 8;
            float ox = d.x + bx, oy = d.y + by;
            float oz = d.z + bx, ow = d.w + by;
            if (ra < N) {
                *(float2*)(OUT + (size_t)ra * ldo + col) = make_float2(ox, oy);
                psx[wn] += ox; psy[wn] += oy;
                pqx[wn] += ox * ox; pqy[wn] += oy * oy;
            }
            if (rb < N) {
                *(float2*)(OUT + (size_t)rb * ldo + col) = make_float2(oz, ow);
                psx[wn] += oz; psy[wn] += ow;
                pqx[wn] += oz * oz; pqy[wn] += ow * ow;
            }
        }
    }
    #pragma unroll
    for (int wn = 0; wn < 8; wn++) {
        #pragma unroll
        for (int o = 4; o <= 16; o <<= 1) {
            psx[wn] += __shfl_xor_sync(0xffffffffu, psx[wn], o);
            psy[wn] += __shfl_xor_sync(0xffffffffu, psy[wn], o);
            pqx[wn] += __shfl_xor_sync(0xffffffffu, pqx[wn], o);
            pqy[wn] += __shfl_xor_sync(0xffffffffu, pqy[wn], o);
        }
    }
    if (lane < 4) {
        #pragma unroll
        for (int wn = 0; wn < 8; wn++) {
            int col = n0 + nBase + wn * 8 + 2 * lane;
            atomicAdd(&g_colsum[col],     psx[wn]);
            atomicAdd(&g_colsum[col + 1], psy[wn]);
            atomicAdd(&g_colsq[col],      pqx[wn]);
            atomicAdd(&g_colsq[col + 1],  pqy[wn]);
        }
    }
}

__global__ void bnfin_k(const float* __restrict__ gamma,
                        const float* __restrict__ beta, int N) {
    int c = blockIdx.x * blockDim.x + threadIdx.x;
    float invN = 1.0f / (float)N;
    float mu  = g_colsum[c] * invN;
    float var = g_colsq[c] * invN - mu * mu;
    float sc  = gamma[c] * rsqrtf(var + 1e-5f);
    g_scale[c] = sc;
    g_shift[c] = beta[c] - mu * sc;
}

// GEMM2: OUT[N,128] = BN(HT[:,koff:+256]) [relu] @ W[256,128] + b2
__global__ void __launch_bounds__(256) gemm2_k(
    const float* __restrict__ HT, const float* __restrict__ W,
    const float* __restrict__ bias, float* __restrict__ OUT,
    int N, int ldh, int koff, int relu) {
    __shared__ unsigned Ah[8 * KW], Al[8 * KW], Bh[8 * KW], Bl[8 * KW];
    __shared__ float Sa[128 * SAW], Sb[16 * SBW];
    int tid  = threadIdx.x;
    int row0 = blockIdx.y * BM;
    int lane = tid & 31, wid = tid >> 5;
    int lk = lane & 3, lm = lane >> 2;
    int warpM = wid & 3, warpN = wid >> 2;
    int mBase = warpM * 32, nBase = warpN * 64;
    float4 acc[2][8];
    #pragma unroll
    for (int i = 0; i < 2; i++)
        #pragma unroll
        for (int j = 0; j < 8; j++) acc[i][j] = make_float4(0.f,0.f,0.f,0.f);

    auto issue = [&](int kk) {
        #pragma unroll
        for (int h = 0; h < 2; h++) {
            int c = h * 256 + tid;
            int m = c >> 2, kq = (c & 3) * 4;
            int rg = row0 + m;
            bool v = rg < N;
            cp16z(Sa + m * SAW + kq,
                  HT + (size_t)(v ? rg : 0) * ldh + koff + kk + kq, v);
            int k = c >> 5, nq = (c & 31) * 4;
            cp16(Sb + k * SBW + nq, W + (size_t)(kk + k) * 128 + nq);
        }
        CP_COMMIT();
    };
    issue(0);

    for (int kk = 0; kk < 256; kk += BK) {
        CP_WAIT0();
        __syncthreads();
        #pragma unroll
        for (int h = 0; h < 2; h++) {
            int idx = h * 256 + tid;
            int m  = idx & 127;
            int kq = (idx >> 7) * 4;
            float4 a = *(float4*)(Sa + m * SAW + kq);
            float4 sc4 = *(const float4*)(g_scale + koff + kk + kq);
            float4 sh4 = *(const float4*)(g_shift + koff + kk + kq);
            a.x = a.x * sc4.x + sh4.x;
            a.y = a.y * sc4.y + sh4.y;
            a.z = a.z * sc4.z + sh4.z;
            a.w = a.w * sc4.w + sh4.w;
            if (relu) {
                a.x = fmaxf(a.x, 0.f); a.y = fmaxf(a.y, 0.f);
                a.z = fmaxf(a.z, 0.f); a.w = fmaxf(a.w, 0.f);
            }
            unsigned wh0, wl0, wh1, wl1;
            bfsplit2(a.x, a.y, wh0, wl0);
            bfsplit2(a.z, a.w, wh1, wl1);
            int aw = (kq >> 1) * KW + m;
            Ah[aw] = wh0; Al[aw] = wl0;
            Ah[aw + KW] = wh1; Al[aw + KW] = wl1;
            float b0 = Sb[(kq + 0) * SBW + m];
            float b1 = Sb[(kq + 1) * SBW + m];
            float b2 = Sb[(kq + 2) * SBW + m];
            float b3 = Sb[(kq + 3) * SBW + m];
            bfsplit2(b0, b1, wh0, wl0);
            bfsplit2(b2, b3, wh1, wl1);
            Bh[aw] = wh0; Bl[aw] = wl0;
            Bh[aw + KW] = wh1; Bl[aw + KW] = wl1;
        }
        __syncthreads();
        if (kk + BK < 256) issue(kk + BK);
        MMA_PHASE(Ah, Al, Bh, Bl)
    }

    #pragma unroll
    for (int wn = 0; wn < 8; wn++) {
        int col = nBase + wn * 8 + 2 * lk;
        float bx = bias[col], by = bias[col + 1];
        #pragma unroll
        for (int wm = 0; wm < 2; wm++) {
            float4 d = acc[wm][wn];
            int ra = row0 + mBase + wm * 16 + lm;
            int rb = ra + 8;
            if (ra < N)
                *(float2*)(OUT + (size_t)ra * 128 + col) = make_float2(d.x + bx, d.y + by);
            if (rb < N)
                *(float2*)(OUT + (size_t)rb * 128 + col) = make_float2(d.z + bx, d.w + by);
        }
    }
}

// ---------------------------------------------------------------------------
// z epilogue and small kernels.
// ---------------------------------------------------------------------------
__global__ void z_k(const float* __restrict__ MEAN, const float* __restrict__ LS,
                    const float* __restrict__ NOISE, const int* __restrict__ batch,
                    const float* __restrict__ Wn, const float* __restrict__ Wc,
                    int N) {
    __shared__ float klred[8];
    int lane = threadIdx.x & 31;
    int w    = threadIdx.x >> 5;
    int row  = blockIdx.x * 8 + w;
    float klp = 0.f;
    if (row < N) {
        size_t off = (size_t)row * 128 + lane * 4;
        float4 m4 = *(const float4*)(MEAN + off);
        float4 l4 = *(const float4*)(LS + off);
        float4 n4 = *(const float4*)(NOISE + off);
        float4 e4 = make_float4(expf(l4.x), expf(l4.y), expf(l4.z), expf(l4.w));
        float4 z4 = make_float4(n4.x * e4.x + m4.x, n4.y * e4.y + m4.y,
                                n4.z * e4.z + m4.z, n4.w * e4.w + m4.w);
        float4 wa = *(const float4*)(Wc + lane * 4);
        float4 wb = *(const float4*)(Wc + 128 + lane * 4);
        float4 wn = *(const float4*)(Wn + lane * 4);
        float up = z4.x * wa.x + z4.y * wa.y + z4.z * wa.z + z4.w * wa.w;
        float vp = z4.x * wb.x + z4.y * wb.y + z4.z * wb.z + z4.w * wb.w;
        float sp = z4.x * wn.x + z4.y * wn.y + z4.z * wn.z + z4.w * wn.w;
        klp = (1.f + 2.f * l4.x - m4.x * m4.x - e4.x * e4.x)
            + (1.f + 2.f * l4.y - m4.y * m4.y - e4.y * e4.y)
            + (1.f + 2.f * l4.z - m4.z * m4.z - e4.z * e4.z)
            + (1.f + 2.f * l4.w - m4.w * m4.w - e4.w * e4.w);
        #pragma unroll
        for (int o = 16; o > 0; o >>= 1) {
            up  += __shfl_xor_sync(0xffffffffu, up,  o);
            vp  += __shfl_xor_sync(0xffffffffu, vp,  o);
            sp  += __shfl_xor_sync(0xffffffffu, sp,  o);
            klp += __shfl_xor_sync(0xffffffffu, klp, o);
        }
        if (lane == 0) {
            g_u[row] = up;
            g_v[row] = vp;
            int b = batch[row];
            atomicAdd(&g_pool[b], sp);
            atomicAdd(&g_cnt[b], 1.0f);
        }
    }
    if (lane == 0) klred[w] = (row < N) ? klp : 0.f;
    __syncthreads();
    if (threadIdx.x == 0) {
        float t = 0.f;
        #pragma unroll
        for (int i = 0; i < 8; i++) t += klred[i];
        atomicAdd(&g_acc[0], t);
    }
}

__global__ void num_k(const float* __restrict__ bridge_num,
                      const float* __restrict__ bnp,
                      float* __restrict__ out_np, int G) {
    __shared__ float red[256];
    int g = blockIdx.x * 256 + threadIdx.x;
    float d = 0.f;
    if (g < G) {
        float np = g_pool[g] / g_cnt[g] + bnp[0];
        out_np[g] = np;
        d = fabsf(np - bridge_num[g]);
    }
    red[threadIdx.x] = d;
    __syncthreads();
    for (int s = 128; s > 0; s >>= 1) {
        if (threadIdx.x < s) red[threadIdx.x] += red[threadIdx.x + s];
        __syncthreads();
    }
    if (threadIdx.x == 0) atomicAdd(&g_acc[1], red[0]);
}

__global__ void apred_k(const int* __restrict__ bidx,
                        const float* __restrict__ bcp,
                        float* __restrict__ out, int P) {
    int p = blockIdx.x * 256 + threadIdx.x;
    if (p >= P) return;
    int i = __ldg(bidx + p);
    int j = __ldg(bidx + P + p);
    float logit = g_u[i] + g_v[j] + bcp[0];
    out[p] = 1.0f / (1.0f + expf(-logit));
}

__global__ void fin_k(float* __restrict__ out, int P, int N, int G) {
    out[P]     = 0.5f * g_acc[0] / ((float)N * (float)N);
    out[P + 1] = g_acc[1] / (float)G;
}

// ---------------------------------------------------------------------------
// Launcher
// ---------------------------------------------------------------------------
extern "C" void kernel_launch(void* const* d_in, const int* in_sizes, int n_in,
                              void* d_out, int out_size) {
    const float* x          = (const float*)d_in[0];
    const int*   ei         = (const int*)  d_in[1];
    const int*   batch      = (const int*)  d_in[2];
    const float* bridge_num = (const float*)d_in[3];
    const int*   bidx       = (const int*)  d_in[4];
    const float* noise      = (const float*)d_in[5];
    const float* W1s        = (const float*)d_in[6];
    const float* b1s        = (const float*)d_in[7];
    const float* gammas     = (const float*)d_in[8];
    const float* betas      = (const float*)d_in[9];
    const float* W2s        = (const float*)d_in[10];
    const float* b2s        = (const float*)d_in[11];
    const float* Wn         = (const float*)d_in[12];
    const float* bnp        = (const float*)d_in[13];
    const float* Wc         = (const float*)d_in[14];
    const float* bcp        = (const float*)d_in[15];
    float* out = (float*)d_out;

    int N = in_sizes[0] / 128;
    int E = in_sizes[1] / 2;
    int G = in_sizes[3];
    int P = in_sizes[4] / 2;

    float *agg, *ht, *h1, *h2, *mean, *ls, *colsum, *colsq, *pool, *cnt, *acc;
    cudaGetSymbolAddress((void**)&agg,    g_agg);
    cudaGetSymbolAddress((void**)&ht,     g_ht);
    cudaGetSymbolAddress((void**)&h1,     g_h1);
    cudaGetSymbolAddress((void**)&h2,     g_h2);
    cudaGetSymbolAddress((void**)&mean,   g_mean);
    cudaGetSymbolAddress((void**)&ls,     g_ls);
    cudaGetSymbolAddress((void**)&colsum, g_colsum);
    cudaGetSymbolAddress((void**)&colsq,  g_colsq);
    cudaGetSymbolAddress((void**)&pool,   g_pool);
    cudaGetSymbolAddress((void**)&cnt,    g_cnt);
    cudaGetSymbolAddress((void**)&acc,    g_acc);

    int rb = (N + BM - 1) / BM;
    int scat_blocks = (E * 32 + 511) / 512;

    // ---- layer 0 ----
    cudaMemsetAsync(agg, 0, (size_t)N * 128 * sizeof(float));
    scatter_k<<<scat_blocks, 512>>>(x, ei, E);
    cudaMemsetAsync(colsum, 0, 512 * sizeof(float));
    cudaMemsetAsync(colsq,  0, 512 * sizeof(float));
    gemm1_k<<<dim3(2, rb), 256>>>(x, W1s, W1s, b1s, ht, N, 256);
    bnfin_k<<<1, 256>>>(gammas, betas, N);
    gemm2_k<<<dim3(1, rb), 256>>>(ht, W2s, b2s, h1, N, 256, 0, 1);

    // ---- layer 1 ----
    cudaMemsetAsync(agg, 0, (size_t)N * 128 * sizeof(float));
    scatter_k<<<scat_blocks, 512>>>(h1, ei, E);
    cudaMemsetAsync(colsum, 0, 512 * sizeof(float));
    cudaMemsetAsync(colsq,  0, 512 * sizeof(float));
    gemm1_k<<<dim3(2, rb), 256>>>(h1, W1s + 1 * 128 * 256, W1s, b1s + 256, ht, N, 256);
    bnfin_k<<<1, 256>>>(gammas + 256, betas + 256, N);
    gemm2_k<<<dim3(1, rb), 256>>>(ht, W2s + 1 * 256 * 128, b2s + 128, h2, N, 256, 0, 1);

    // ---- layers 2+3 combined (shared A = h2 + agg(h2)) ----
    cudaMemsetAsync(agg, 0, (size_t)N * 128 * sizeof(float));
    scatter_k<<<scat_blocks, 512>>>(h2, ei, E);
    cudaMemsetAsync(colsum, 0, 512 * sizeof(float));
    cudaMemsetAsync(colsq,  0, 512 * sizeof(float));
    gemm1_k<<<dim3(4, rb), 256>>>(h2, W1s + 2 * 128 * 256, W1s + 3 * 128 * 256,
                                  b1s + 512, ht, N, 512);
    bnfin_k<<<1, 512>>>(gammas + 512, betas + 512, N);
    gemm2_k<<<dim3(1, rb), 256>>>(ht, W2s + 2 * 256 * 128, b2s + 256, mean, N, 512, 0,   0);
    gemm2_k<<<dim3(1, rb), 256>>>(ht, W2s + 3 * 256 * 128, b2s + 384, ls,   N, 512, 256, 0);

    // ---- epilogue ----
    cudaMemsetAsync(pool, 0, G * sizeof(float));
    cudaMemsetAsync(cnt,  0, G * sizeof(float));
    cudaMemsetAsync(acc,  0, 2 * sizeof(float));
    z_k<<<(N + 7) / 8, 256>>>(mean, ls, noise, batch, Wn, Wc, N);
    num_k<<<(G + 255) / 256, 256>>>(bridge_num, bnp, out + P + 2, G);
    apred_k<<<(P + 255) / 256, 256>>>(bidx, bcp, out, P);
    fin_k<<<1, 1>>>(out, P, N, G);
}

// round 12
// speedup vs baseline: 1.9357x; 1.3980x over previous
#include <cuda_runtime.h>
#include <cuda_bf16.h>
#include <math.h>

// ---------------------------------------------------------------------------
// N=90000, D=H=128, 2H=256, E=1.44M, G=3000, P=675000.
// ---------------------------------------------------------------------------
#define MAXN 90112
#define MAXG 4096
#define MAXE 1500000

__device__ float g_agg [MAXN * 128];
__device__ float g_ht  [MAXN * 512];
__device__ float g_h1  [MAXN * 128];
__device__ float g_h2  [MAXN * 128];
__device__ float g_mean[MAXN * 128];
__device__ float g_ls  [MAXN * 128];
__device__ float g_u   [MAXN];
__device__ float g_v   [MAXN];
__device__ float g_colsum[512];
__device__ float g_colsq [512];
__device__ float g_scale [512];
__device__ float g_shift [512];
__device__ float g_pool[MAXG];
__device__ float g_cnt [MAXG];
__device__ float g_acc [2];
// CSR structures (built once per launch)
__device__ int g_deg [MAXN];
__device__ int g_off [MAXN];
__device__ int g_cur [MAXN];
__device__ int g_elist[MAXE];
__device__ int g_bsum[512];
__device__ int g_bex [512];

// ---------------------------------------------------------------------------
// bf16 split + mma helpers.
// ---------------------------------------------------------------------------
__device__ __forceinline__ void bfsplit2(float e0, float e1,
                                         unsigned& wh, unsigned& wl) {
    __nv_bfloat16 h0 = __float2bfloat16_rn(e0);
    __nv_bfloat16 h1 = __float2bfloat16_rn(e1);
    __nv_bfloat16 l0 = __float2bfloat16_rn(e0 - __bfloat162float(h0));
    __nv_bfloat16 l1 = __float2bfloat16_rn(e1 - __bfloat162float(h1));
    __nv_bfloat162 vh = __nv_bfloat162(h0, h1);
    __nv_bfloat162 vl = __nv_bfloat162(l0, l1);
    wh = *(unsigned*)&vh;
    wl = *(unsigned*)&vl;
}

__device__ __forceinline__ void mma_bf16(float4& d, const unsigned* a,
                                         unsigned b0, unsigned b1) {
    asm volatile(
        "mma.sync.aligned.m16n8k16.row.col.f32.bf16.bf16.f32 "
        "{%0,%1,%2,%3},{%4,%5,%6,%7},{%8,%9},{%0,%1,%2,%3};"
        : "+f"(d.x), "+f"(d.y), "+f"(d.z), "+f"(d.w)
        : "r"(a[0]), "r"(a[1]), "r"(a[2]), "r"(a[3]), "r"(b0), "r"(b1));
}

// cp.async helpers (16B, L1-bypass; optional zero-fill via src-size=0)
__device__ __forceinline__ void cp16(void* dst, const void* src) {
    unsigned d = (unsigned)__cvta_generic_to_shared(dst);
    asm volatile("cp.async.cg.shared.global [%0], [%1], 16;" :: "r"(d), "l"(src));
}
__device__ __forceinline__ void cp16z(void* dst, const void* src, bool valid) {
    unsigned d = (unsigned)__cvta_generic_to_shared(dst);
    int sz = valid ? 16 : 0;
    asm volatile("cp.async.cg.shared.global [%0], [%1], 16, %2;"
                 :: "r"(d), "l"(src), "r"(sz));
}
#define CP_COMMIT() asm volatile("cp.async.commit_group;")
#define CP_WAIT0()  asm volatile("cp.async.wait_group 0;")

// ---------------------------------------------------------------------------
// CSR build: histogram -> block scan (3 kernels) -> fill.
// ---------------------------------------------------------------------------
__global__ void hist_k(const int* __restrict__ ei, int E, int N) {
    int i = blockIdx.x * blockDim.x + threadIdx.x;
    if (i < E) atomicAdd(&g_deg[__ldg(ei + E + i)], 1);
}

__global__ void scan1_k(int N) {            // per-block sums of deg
    __shared__ int red[256];
    int i = blockIdx.x * 256 + threadIdx.x;
    red[threadIdx.x] = (i < N) ? g_deg[i] : 0;
    __syncthreads();
    for (int s = 128; s > 0; s >>= 1) {
        if (threadIdx.x < s) red[threadIdx.x] += red[threadIdx.x + s];
        __syncthreads();
    }
    if (threadIdx.x == 0) g_bsum[blockIdx.x] = red[0];
}

__global__ void scan2_k(int NB) {           // exclusive scan of block sums
    __shared__ int s0[512], s1[512];
    int t = threadIdx.x;
    int v = (t < NB) ? g_bsum[t] : 0;
    s0[t] = v;
    __syncthreads();
    int* src = s0; int* dst = s1;
    for (int o = 1; o < 512; o <<= 1) {
        int x = src[t];
        if (t >= o) x += src[t - o];
        dst[t] = x;
        __syncthreads();
        int* tmp = src; src = dst; dst = tmp;
    }
    if (t < NB) g_bex[t] = src[t] - v;      // exclusive
}

__global__ void scan3_k(int N) {            // per-element offsets
    __shared__ int s0[256], s1[256];
    int t = threadIdx.x;
    int i = blockIdx.x * 256 + t;
    int v = (i < N) ? g_deg[i] : 0;
    s0[t] = v;
    __syncthreads();
    int* src = s0; int* dst = s1;
    for (int o = 1; o < 256; o <<= 1) {
        int x = src[t];
        if (t >= o) x += src[t - o];
        dst[t] = x;
        __syncthreads();
        int* tmp = src; src = dst; dst = tmp;
    }
    if (i < N) {
        int off = g_bex[blockIdx.x] + src[t] - v;
        g_off[i] = off;
        g_cur[i] = off;
    }
}

__global__ void fill_k(const int* __restrict__ ei, int E) {
    int i = blockIdx.x * blockDim.x + threadIdx.x;
    if (i >= E) return;
    int s = __ldg(ei + i);
    int d = __ldg(ei + E + i);
    int p = atomicAdd(&g_cur[d], 1);
    g_elist[p] = s;
}

// ---------------------------------------------------------------------------
// Gather aggregation: one warp per node, sum in-neighbor rows, write once.
// ---------------------------------------------------------------------------
__global__ void gather_k(const float* __restrict__ X, int N) {
    int gw   = (blockIdx.x * blockDim.x + threadIdx.x) >> 5;
    int lane = threadIdx.x & 31;
    if (gw >= N) return;
    int base = g_off[gw];
    int dg   = g_deg[gw];
    float4 acc = make_float4(0.f, 0.f, 0.f, 0.f);
    int j = 0;
    for (; j + 2 <= dg; j += 2) {
        int s0 = __ldg(g_elist + base + j);
        int s1 = __ldg(g_elist + base + j + 1);
        float4 a = *(const float4*)(X + (size_t)s0 * 128 + lane * 4);
        float4 b = *(const float4*)(X + (size_t)s1 * 128 + lane * 4);
        acc.x += a.x + b.x; acc.y += a.y + b.y;
        acc.z += a.z + b.z; acc.w += a.w + b.w;
    }
    if (j < dg) {
        int s0 = __ldg(g_elist + base + j);
        float4 a = *(const float4*)(X + (size_t)s0 * 128 + lane * 4);
        acc.x += a.x; acc.y += a.y; acc.z += a.z; acc.w += a.w;
    }
    *(float4*)(g_agg + (size_t)gw * 128 + lane * 4) = acc;
}

// ---------------------------------------------------------------------------
// bf16x3 GEMM with cp.async staging. BK=16, 128x128 tile, 8 warps (4m x 2n),
// warp 32x64, m16n8k16.  Split operands [k2][m]/[k2][n] stride 136 (words).
// ---------------------------------------------------------------------------
#define BM 128
#define BN 128
#define BK 16
#define KW 136
#define SAW 20
#define SBW 132

#define MMA3(ACC, AH, AL, BH0, BH1, BL0, BL1)  \
    do { mma_bf16(ACC, AH, BH0, BH1);          \
         mma_bf16(ACC, AL, BH0, BH1);          \
         mma_bf16(ACC, AH, BL0, BL1); } while (0)

#define MMA_PHASE(Ah, Al, Bh, Bl)                                           \
    {                                                                       \
        unsigned ah[2][4], al[2][4];                                        \
        _Pragma("unroll")                                                   \
        for (int wm = 0; wm < 2; wm++) {                                    \
            int mr = mBase + wm * 16 + lm;                                  \
            ah[wm][0] = Ah[lk * KW + mr];                                   \
            ah[wm][1] = Ah[lk * KW + mr + 8];                               \
            ah[wm][2] = Ah[(lk + 4) * KW + mr];                             \
            ah[wm][3] = Ah[(lk + 4) * KW + mr + 8];                         \
            al[wm][0] = Al[lk * KW + mr];                                   \
            al[wm][1] = Al[lk * KW + mr + 8];                               \
            al[wm][2] = Al[(lk + 4) * KW + mr];                             \
            al[wm][3] = Al[(lk + 4) * KW + mr + 8];                         \
        }                                                                   \
        _Pragma("unroll")                                                   \
        for (int wn = 0; wn < 8; wn++) {                                    \
            int nc = nBase + wn * 8 + lm;                                   \
            unsigned bh0 = Bh[lk * KW + nc], bh1 = Bh[(lk + 4) * KW + nc];  \
            unsigned bl0 = Bl[lk * KW + nc], bl1 = Bl[(lk + 4) * KW + nc];  \
            _Pragma("unroll")                                               \
            for (int wm = 0; wm < 2; wm++)                                  \
                MMA3(acc[wm][wn], ah[wm], al[wm], bh0, bh1, bl0, bl1);      \
        }                                                                   \
    }

// GEMM1: OUT[:, n0:n0+128] = (X+agg) @ W + bias ; fused colsum/colsq stats.
__global__ void __launch_bounds__(256) gemm1_k(
    const float* __restrict__ X, const float* __restrict__ Wa,
    const float* __restrict__ Wb, const float* __restrict__ bias,
    float* __restrict__ OUT, int N, int ldo) {
    __shared__ unsigned Ah[8 * KW], Al[8 * KW], Bh[8 * KW], Bl[8 * KW];
    __shared__ float SaX[128 * SAW], SaG[128 * SAW], Sb[16 * SBW];
    int tid  = threadIdx.x;
    int row0 = blockIdx.y * BM;
    int n0   = blockIdx.x * BN;
    const float* W = (n0 < 256) ? Wa : Wb;
    int nbase = (n0 < 256) ? n0 : (n0 - 256);
    int lane = tid & 31, wid = tid >> 5;
    int lk = lane & 3, lm = lane >> 2;
    int warpM = wid & 3, warpN = wid >> 2;
    int mBase = warpM * 32, nBase = warpN * 64;
    float4 acc[2][8];
    #pragma unroll
    for (int i = 0; i < 2; i++)
        #pragma unroll
        for (int j = 0; j < 8; j++) acc[i][j] = make_float4(0.f,0.f,0.f,0.f);

    auto issue = [&](int kk) {
        #pragma unroll
        for (int h = 0; h < 2; h++) {
            int c = h * 256 + tid;
            int m = c >> 2, kq = (c & 3) * 4;
            int rg = row0 + m;
            bool v = rg < N;
            size_t off = (size_t)(v ? rg : 0) * 128 + kk + kq;
            cp16z(SaX + m * SAW + kq, X + off, v);
            cp16z(SaG + m * SAW + kq, g_agg + off, v);
            int k = c >> 5, nq = (c & 31) * 4;
            cp16(Sb + k * SBW + nq, W + (size_t)(kk + k) * 256 + nbase + nq);
        }
        CP_COMMIT();
    };
    issue(0);

    for (int kk = 0; kk < 128; kk += BK) {
        CP_WAIT0();
        __syncthreads();
        #pragma unroll
        for (int h = 0; h < 2; h++) {
            int idx = h * 256 + tid;
            int m  = idx & 127;
            int kq = (idx >> 7) * 4;
            float4 xv = *(float4*)(SaX + m * SAW + kq);
            float4 av = *(float4*)(SaG + m * SAW + kq);
            float4 a = make_float4(xv.x + av.x, xv.y + av.y,
                                   xv.z + av.z, xv.w + av.w);
            unsigned wh0, wl0, wh1, wl1;
            bfsplit2(a.x, a.y, wh0, wl0);
            bfsplit2(a.z, a.w, wh1, wl1);
            int aw = (kq >> 1) * KW + m;
            Ah[aw] = wh0; Al[aw] = wl0;
            Ah[aw + KW] = wh1; Al[aw + KW] = wl1;
            float b0 = Sb[(kq + 0) * SBW + m];
            float b1 = Sb[(kq + 1) * SBW + m];
            float b2 = Sb[(kq + 2) * SBW + m];
            float b3 = Sb[(kq + 3) * SBW + m];
            bfsplit2(b0, b1, wh0, wl0);
            bfsplit2(b2, b3, wh1, wl1);
            Bh[aw] = wh0; Bl[aw] = wl0;
            Bh[aw + KW] = wh1; Bl[aw + KW] = wl1;
        }
        __syncthreads();
        if (kk + BK < 128) issue(kk + BK);
        MMA_PHASE(Ah, Al, Bh, Bl)
    }

    float psx[8]={}, psy[8]={}, pqx[8]={}, pqy[8]={};
    #pragma unroll
    for (int wn = 0; wn < 8; wn++) {
        int col = n0 + nBase + wn * 8 + 2 * lk;
        float bx = bias[col], by = bias[col + 1];
        #pragma unroll
        for (int wm = 0; wm < 2; wm++) {
            float4 d = acc[wm][wn];
            int ra = row0 + mBase + wm * 16 + lm;
            int rb = ra + 8;
            float ox = d.x + bx, oy = d.y + by;
            float oz = d.z + bx, ow = d.w + by;
            if (ra < N) {
                *(float2*)(OUT + (size_t)ra * ldo + col) = make_float2(ox, oy);
                psx[wn] += ox; psy[wn] += oy;
                pqx[wn] += ox * ox; pqy[wn] += oy * oy;
            }
            if (rb < N) {
                *(float2*)(OUT + (size_t)rb * ldo + col) = make_float2(oz, ow);
                psx[wn] += oz; psy[wn] += ow;
                pqx[wn] += oz * oz; pqy[wn] += ow * ow;
            }
        }
    }
    #pragma unroll
    for (int wn = 0; wn < 8; wn++) {
        #pragma unroll
        for (int o = 4; o <= 16; o <<= 1) {
            psx[wn] += __shfl_xor_sync(0xffffffffu, psx[wn], o);
            psy[wn] += __shfl_xor_sync(0xffffffffu, psy[wn], o);
            pqx[wn] += __shfl_xor_sync(0xffffffffu, pqx[wn], o);
            pqy[wn] += __shfl_xor_sync(0xffffffffu, pqy[wn], o);
        }
    }
    if (lane < 4) {
        #pragma unroll
        for (int wn = 0; wn < 8; wn++) {
            int col = n0 + nBase + wn * 8 + 2 * lane;
            atomicAdd(&g_colsum[col],     psx[wn]);
            atomicAdd(&g_colsum[col + 1], psy[wn]);
            atomicAdd(&g_colsq[col],      pqx[wn]);
            atomicAdd(&g_colsq[col + 1],  pqy[wn]);
        }
    }
}

__global__ void bnfin_k(const float* __restrict__ gamma,
                        const float* __restrict__ beta, int N) {
    int c = blockIdx.x * blockDim.x + threadIdx.x;
    float invN = 1.0f / (float)N;
    float mu  = g_colsum[c] * invN;
    float var = g_colsq[c] * invN - mu * mu;
    float sc  = gamma[c] * rsqrtf(var + 1e-5f);
    g_scale[c] = sc;
    g_shift[c] = beta[c] - mu * sc;
}

// GEMM2: OUT[N,128] = BN(HT[:,koff:+256]) [relu] @ W[256,128] + b2
__global__ void __launch_bounds__(256) gemm2_k(
    const float* __restrict__ HT, const float* __restrict__ W,
    const float* __restrict__ bias, float* __restrict__ OUT,
    int N, int ldh, int koff, int relu) {
    __shared__ unsigned Ah[8 * KW], Al[8 * KW], Bh[8 * KW], Bl[8 * KW];
    __shared__ float Sa[128 * SAW], Sb[16 * SBW];
    int tid  = threadIdx.x;
    int row0 = blockIdx.y * BM;
    int lane = tid & 31, wid = tid >> 5;
    int lk = lane & 3, lm = lane >> 2;
    int warpM = wid & 3, warpN = wid >> 2;
    int mBase = warpM * 32, nBase = warpN * 64;
    float4 acc[2][8];
    #pragma unroll
    for (int i = 0; i < 2; i++)
        #pragma unroll
        for (int j = 0; j < 8; j++) acc[i][j] = make_float4(0.f,0.f,0.f,0.f);

    auto issue = [&](int kk) {
        #pragma unroll
        for (int h = 0; h < 2; h++) {
            int c = h * 256 + tid;
            int m = c >> 2, kq = (c & 3) * 4;
            int rg = row0 + m;
            bool v = rg < N;
            cp16z(Sa + m * SAW + kq,
                  HT + (size_t)(v ? rg : 0) * ldh + koff + kk + kq, v);
            int k = c >> 5, nq = (c & 31) * 4;
            cp16(Sb + k * SBW + nq, W + (size_t)(kk + k) * 128 + nq);
        }
        CP_COMMIT();
    };
    issue(0);

    for (int kk = 0; kk < 256; kk += BK) {
        CP_WAIT0();
        __syncthreads();
        #pragma unroll
        for (int h = 0; h < 2; h++) {
            int idx = h * 256 + tid;
            int m  = idx & 127;
            int kq = (idx >> 7) * 4;
            float4 a = *(float4*)(Sa + m * SAW + kq);
            float4 sc4 = *(const float4*)(g_scale + koff + kk + kq);
            float4 sh4 = *(const float4*)(g_shift + koff + kk + kq);
            a.x = a.x * sc4.x + sh4.x;
            a.y = a.y * sc4.y + sh4.y;
            a.z = a.z * sc4.z + sh4.z;
            a.w = a.w * sc4.w + sh4.w;
            if (relu) {
                a.x = fmaxf(a.x, 0.f); a.y = fmaxf(a.y, 0.f);
                a.z = fmaxf(a.z, 0.f); a.w = fmaxf(a.w, 0.f);
            }
            unsigned wh0, wl0, wh1, wl1;
            bfsplit2(a.x, a.y, wh0, wl0);
            bfsplit2(a.z, a.w, wh1, wl1);
            int aw = (kq >> 1) * KW + m;
            Ah[aw] = wh0; Al[aw] = wl0;
            Ah[aw + KW] = wh1; Al[aw + KW] = wl1;
            float b0 = Sb[(kq + 0) * SBW + m];
            float b1 = Sb[(kq + 1) * SBW + m];
            float b2 = Sb[(kq + 2) * SBW + m];
            float b3 = Sb[(kq + 3) * SBW + m];
            bfsplit2(b0, b1, wh0, wl0);
            bfsplit2(b2, b3, wh1, wl1);
            Bh[aw] = wh0; Bl[aw] = wl0;
            Bh[aw + KW] = wh1; Bl[aw + KW] = wl1;
        }
        __syncthreads();
        if (kk + BK < 256) issue(kk + BK);
        MMA_PHASE(Ah, Al, Bh, Bl)
    }

    #pragma unroll
    for (int wn = 0; wn < 8; wn++) {
        int col = nBase + wn * 8 + 2 * lk;
        float bx = bias[col], by = bias[col + 1];
        #pragma unroll
        for (int wm = 0; wm < 2; wm++) {
            float4 d = acc[wm][wn];
            int ra = row0 + mBase + wm * 16 + lm;
            int rb = ra + 8;
            if (ra < N)
                *(float2*)(OUT + (size_t)ra * 128 + col) = make_float2(d.x + bx, d.y + by);
            if (rb < N)
                *(float2*)(OUT + (size_t)rb * 128 + col) = make_float2(d.z + bx, d.w + by);
        }
    }
}

// ---------------------------------------------------------------------------
// z epilogue and small kernels.
// ---------------------------------------------------------------------------
__global__ void z_k(const float* __restrict__ MEAN, const float* __restrict__ LS,
                    const float* __restrict__ NOISE, const int* __restrict__ batch,
                    const float* __restrict__ Wn, const float* __restrict__ Wc,
                    int N) {
    __shared__ float klred[8];
    int lane = threadIdx.x & 31;
    int w    = threadIdx.x >> 5;
    int row  = blockIdx.x * 8 + w;
    float klp = 0.f;
    if (row < N) {
        size_t off = (size_t)row * 128 + lane * 4;
        float4 m4 = *(const float4*)(MEAN + off);
        float4 l4 = *(const float4*)(LS + off);
        float4 n4 = *(const float4*)(NOISE + off);
        float4 e4 = make_float4(expf(l4.x), expf(l4.y), expf(l4.z), expf(l4.w));
        float4 z4 = make_float4(n4.x * e4.x + m4.x, n4.y * e4.y + m4.y,
                                n4.z * e4.z + m4.z, n4.w * e4.w + m4.w);
        float4 wa = *(const float4*)(Wc + lane * 4);
        float4 wb = *(const float4*)(Wc + 128 + lane * 4);
        float4 wn = *(const float4*)(Wn + lane * 4);
        float up = z4.x * wa.x + z4.y * wa.y + z4.z * wa.z + z4.w * wa.w;
        float vp = z4.x * wb.x + z4.y * wb.y + z4.z * wb.z + z4.w * wb.w;
        float sp = z4.x * wn.x + z4.y * wn.y + z4.z * wn.z + z4.w * wn.w;
        klp = (1.f + 2.f * l4.x - m4.x * m4.x - e4.x * e4.x)
            + (1.f + 2.f * l4.y - m4.y * m4.y - e4.y * e4.y)
            + (1.f + 2.f * l4.z - m4.z * m4.z - e4.z * e4.z)
            + (1.f + 2.f * l4.w - m4.w * m4.w - e4.w * e4.w);
        #pragma unroll
        for (int o = 16; o > 0; o >>= 1) {
            up  += __shfl_xor_sync(0xffffffffu, up,  o);
            vp  += __shfl_xor_sync(0xffffffffu, vp,  o);
            sp  += __shfl_xor_sync(0xffffffffu, sp,  o);
            klp += __shfl_xor_sync(0xffffffffu, klp, o);
        }
        if (lane == 0) {
            g_u[row] = up;
            g_v[row] = vp;
            int b = batch[row];
            atomicAdd(&g_pool[b], sp);
            atomicAdd(&g_cnt[b], 1.0f);
        }
    }
    if (lane == 0) klred[w] = (row < N) ? klp : 0.f;
    __syncthreads();
    if (threadIdx.x == 0) {
        float t = 0.f;
        #pragma unroll
        for (int i = 0; i < 8; i++) t += klred[i];
        atomicAdd(&g_acc[0], t);
    }
}

__global__ void num_k(const float* __restrict__ bridge_num,
                      const float* __restrict__ bnp,
                      float* __restrict__ out_np, int G) {
    __shared__ float red[256];
    int g = blockIdx.x * 256 + threadIdx.x;
    float d = 0.f;
    if (g < G) {
        float np = g_pool[g] / g_cnt[g] + bnp[0];
        out_np[g] = np;
        d = fabsf(np - bridge_num[g]);
    }
    red[threadIdx.x] = d;
    __syncthreads();
    for (int s = 128; s > 0; s >>= 1) {
        if (threadIdx.x < s) red[threadIdx.x] += red[threadIdx.x + s];
        __syncthreads();
    }
    if (threadIdx.x == 0) atomicAdd(&g_acc[1], red[0]);
}

__global__ void apred_k(const int* __restrict__ bidx,
                        const float* __restrict__ bcp,
                        float* __restrict__ out, int P) {
    int p = blockIdx.x * 256 + threadIdx.x;
    if (p >= P) return;
    int i = __ldg(bidx + p);
    int j = __ldg(bidx + P + p);
    float logit = g_u[i] + g_v[j] + bcp[0];
    out[p] = 1.0f / (1.0f + expf(-logit));
}

__global__ void fin_k(float* __restrict__ out, int P, int N, int G) {
    out[P]     = 0.5f * g_acc[0] / ((float)N * (float)N);
    out[P + 1] = g_acc[1] / (float)G;
}

// ---------------------------------------------------------------------------
// Launcher
// ---------------------------------------------------------------------------
extern "C" void kernel_launch(void* const* d_in, const int* in_sizes, int n_in,
                              void* d_out, int out_size) {
    const float* x          = (const float*)d_in[0];
    const int*   ei         = (const int*)  d_in[1];
    const int*   batch      = (const int*)  d_in[2];
    const float* bridge_num = (const float*)d_in[3];
    const int*   bidx       = (const int*)  d_in[4];
    const float* noise      = (const float*)d_in[5];
    const float* W1s        = (const float*)d_in[6];
    const float* b1s        = (const float*)d_in[7];
    const float* gammas     = (const float*)d_in[8];
    const float* betas      = (const float*)d_in[9];
    const float* W2s        = (const float*)d_in[10];
    const float* b2s        = (const float*)d_in[11];
    const float* Wn         = (const float*)d_in[12];
    const float* bnp        = (const float*)d_in[13];
    const float* Wc         = (const float*)d_in[14];
    const float* bcp        = (const float*)d_in[15];
    float* out = (float*)d_out;

    int N = in_sizes[0] / 128;
    int E = in_sizes[1] / 2;
    int G = in_sizes[3];
    int P = in_sizes[4] / 2;

    float *ht, *h1, *h2, *mean, *ls, *colsum, *colsq, *pool, *cnt, *acc;
    int  *deg;
    cudaGetSymbolAddress((void**)&ht,     g_ht);
    cudaGetSymbolAddress((void**)&h1,     g_h1);
    cudaGetSymbolAddress((void**)&h2,     g_h2);
    cudaGetSymbolAddress((void**)&mean,   g_mean);
    cudaGetSymbolAddress((void**)&ls,     g_ls);
    cudaGetSymbolAddress((void**)&colsum, g_colsum);
    cudaGetSymbolAddress((void**)&colsq,  g_colsq);
    cudaGetSymbolAddress((void**)&pool,   g_pool);
    cudaGetSymbolAddress((void**)&cnt,    g_cnt);
    cudaGetSymbolAddress((void**)&acc,    g_acc);
    cudaGetSymbolAddress((void**)&deg,    g_deg);

    int rb = (N + BM - 1) / BM;
    int nb256 = (N + 255) / 256;           // scan blocks (<=512 required)
    int gather_blocks = (N * 32 + 255) / 256;

    // ---- build CSR once (edges fixed across layers) ----
    cudaMemsetAsync(deg, 0, N * sizeof(int));
    hist_k<<<(E + 255) / 256, 256>>>(ei, E, N);
    scan1_k<<<nb256, 256>>>(N);
    scan2_k<<<1, 512>>>(nb256);
    scan3_k<<<nb256, 256>>>(N);
    fill_k<<<(E + 255) / 256, 256>>>(ei, E);

    // ---- layer 0 ----
    gather_k<<<gather_blocks, 256>>>(x, N);
    cudaMemsetAsync(colsum, 0, 512 * sizeof(float));
    cudaMemsetAsync(colsq,  0, 512 * sizeof(float));
    gemm1_k<<<dim3(2, rb), 256>>>(x, W1s, W1s, b1s, ht, N, 256);
    bnfin_k<<<1, 256>>>(gammas, betas, N);
    gemm2_k<<<dim3(1, rb), 256>>>(ht, W2s, b2s, h1, N, 256, 0, 1);

    // ---- layer 1 ----
    gather_k<<<gather_blocks, 256>>>(h1, N);
    cudaMemsetAsync(colsum, 0, 512 * sizeof(float));
    cudaMemsetAsync(colsq,  0, 512 * sizeof(float));
    gemm1_k<<<dim3(2, rb), 256>>>(h1, W1s + 1 * 128 * 256, W1s, b1s + 256, ht, N, 256);
    bnfin_k<<<1, 256>>>(gammas + 256, betas + 256, N);
    gemm2_k<<<dim3(1, rb), 256>>>(ht, W2s + 1 * 256 * 128, b2s + 128, h2, N, 256, 0, 1);

    // ---- layers 2+3 combined (shared A = h2 + agg(h2)) ----
    gather_k<<<gather_blocks, 256>>>(h2, N);
    cudaMemsetAsync(colsum, 0, 512 * sizeof(float));
    cudaMemsetAsync(colsq,  0, 512 * sizeof(float));
    gemm1_k<<<dim3(4, rb), 256>>>(h2, W1s + 2 * 128 * 256, W1s + 3 * 128 * 256,
                                  b1s + 512, ht, N, 512);
    bnfin_k<<<1, 512>>>(gammas + 512, betas + 512, N);
    gemm2_k<<<dim3(1, rb), 256>>>(ht, W2s + 2 * 256 * 128, b2s + 256, mean, N, 512, 0,   0);
    gemm2_k<<<dim3(1, rb), 256>>>(ht, W2s + 3 * 256 * 128, b2s + 384, ls,   N, 512, 256, 0);

    // ---- epilogue ----
    cudaMemsetAsync(pool, 0, G * sizeof(float));
    cudaMemsetAsync(cnt,  0, G * sizeof(float));
    cudaMemsetAsync(acc,  0, 2 * sizeof(float));
    z_k<<<(N + 7) / 8, 256>>>(mean, ls, noise, batch, Wn, Wc, N);
    num_k<<<(G + 255) / 256, 256>>>(bridge_num, bnp, out + P + 2, G);
    apred_k<<<(P + 255) / 256, 256>>>(bidx, bcp, out, P);
    fin_k<<<1, 1>>>(out, P, N, G);
}

// round 13
// speedup vs baseline: 1.9996x; 1.0330x over previous
#include <cuda_runtime.h>
#include <cuda_bf16.h>
#include <math.h>

// ---------------------------------------------------------------------------
// N=90000, D=H=128, 2H=256, E=1.44M, G=3000, P=675000.
// ---------------------------------------------------------------------------
#define MAXN 90112
#define MAXG 4096
#define MAXE 1500000

__device__ float    g_ht  [MAXN * 512];
__device__ float    g_h1  [MAXN * 128];
__device__ float    g_h2  [MAXN * 128];
__device__ float    g_mean[MAXN * 128];
__device__ float    g_ls  [MAXN * 128];
__device__ unsigned g_axh [MAXN * 64];     // pre-split (X+agg) hi, bf16x2 words
__device__ unsigned g_axl [MAXN * 64];     // pre-split (X+agg) lo
__device__ unsigned g_w1h [4 * 256 * 64];  // W1 pre-split [l][n][k2]
__device__ unsigned g_w1l [4 * 256 * 64];
__device__ unsigned g_w2h [4 * 128 * 128]; // W2 pre-split [l][n][k2]
__device__ unsigned g_w2l [4 * 128 * 128];
__device__ float g_u   [MAXN];
__device__ float g_v   [MAXN];
__device__ float g_colsum[512];
__device__ float g_colsq [512];
__device__ float g_scale [512];
__device__ float g_shift [512];
__device__ float g_pool[MAXG];
__device__ float g_cnt [MAXG];
__device__ float g_acc [2];
// CSR structures (built once per launch)
__device__ int g_deg [MAXN];
__device__ int g_off [MAXN];
__device__ int g_cur [MAXN];
__device__ int g_elist[MAXE];
__device__ int g_bsum[512];
__device__ int g_bex [512];

// ---------------------------------------------------------------------------
// bf16 split + mma helpers.
// ---------------------------------------------------------------------------
__device__ __forceinline__ void bfsplit2(float e0, float e1,
                                         unsigned& wh, unsigned& wl) {
    __nv_bfloat16 h0 = __float2bfloat16_rn(e0);
    __nv_bfloat16 h1 = __float2bfloat16_rn(e1);
    __nv_bfloat16 l0 = __float2bfloat16_rn(e0 - __bfloat162float(h0));
    __nv_bfloat16 l1 = __float2bfloat16_rn(e1 - __bfloat162float(h1));
    __nv_bfloat162 vh = __nv_bfloat162(h0, h1);
    __nv_bfloat162 vl = __nv_bfloat162(l0, l1);
    wh = *(unsigned*)&vh;
    wl = *(unsigned*)&vl;
}

__device__ __forceinline__ void mma_bf16(float4& d, const unsigned* a,
                                         unsigned b0, unsigned b1) {
    asm volatile(
        "mma.sync.aligned.m16n8k16.row.col.f32.bf16.bf16.f32 "
        "{%0,%1,%2,%3},{%4,%5,%6,%7},{%8,%9},{%0,%1,%2,%3};"
        : "+f"(d.x), "+f"(d.y), "+f"(d.z), "+f"(d.w)
        : "r"(a[0]), "r"(a[1]), "r"(a[2]), "r"(a[3]), "r"(b0), "r"(b1));
}

__device__ __forceinline__ void cp16(void* dst, const void* src) {
    unsigned d = (unsigned)__cvta_generic_to_shared(dst);
    asm volatile("cp.async.cg.shared.global [%0], [%1], 16;" :: "r"(d), "l"(src));
}
#define CP_COMMIT() asm volatile("cp.async.commit_group;")
#define CP_WAIT0()  asm volatile("cp.async.wait_group 0;")
#define CP_WAIT1()  asm volatile("cp.async.wait_group 1;")

// ---------------------------------------------------------------------------
// CSR build: histogram -> block scan -> fill.
// ---------------------------------------------------------------------------
__global__ void hist_k(const int* __restrict__ ei, int E, int N) {
    int i = blockIdx.x * blockDim.x + threadIdx.x;
    if (i < E) atomicAdd(&g_deg[__ldg(ei + E + i)], 1);
}

__global__ void scan1_k(int N) {
    __shared__ int red[256];
    int i = blockIdx.x * 256 + threadIdx.x;
    red[threadIdx.x] = (i < N) ? g_deg[i] : 0;
    __syncthreads();
    for (int s = 128; s > 0; s >>= 1) {
        if (threadIdx.x < s) red[threadIdx.x] += red[threadIdx.x + s];
        __syncthreads();
    }
    if (threadIdx.x == 0) g_bsum[blockIdx.x] = red[0];
}

__global__ void scan2_k(int NB) {
    __shared__ int s0[512], s1[512];
    int t = threadIdx.x;
    int v = (t < NB) ? g_bsum[t] : 0;
    s0[t] = v;
    __syncthreads();
    int* src = s0; int* dst = s1;
    for (int o = 1; o < 512; o <<= 1) {
        int x = src[t];
        if (t >= o) x += src[t - o];
        dst[t] = x;
        __syncthreads();
        int* tmp = src; src = dst; dst = tmp;
    }
    if (t < NB) g_bex[t] = src[t] - v;
}

__global__ void scan3_k(int N) {
    __shared__ int s0[256], s1[256];
    int t = threadIdx.x;
    int i = blockIdx.x * 256 + t;
    int v = (i < N) ? g_deg[i] : 0;
    s0[t] = v;
    __syncthreads();
    int* src = s0; int* dst = s1;
    for (int o = 1; o < 256; o <<= 1) {
        int x = src[t];
        if (t >= o) x += src[t - o];
        dst[t] = x;
        __syncthreads();
        int* tmp = src; src = dst; dst = tmp;
    }
    if (i < N) {
        int off = g_bex[blockIdx.x] + src[t] - v;
        g_off[i] = off;
        g_cur[i] = off;
    }
}

__global__ void fill_k(const int* __restrict__ ei, int E) {
    int i = blockIdx.x * blockDim.x + threadIdx.x;
    if (i >= E) return;
    int s = __ldg(ei + i);
    int d = __ldg(ei + E + i);
    int p = atomicAdd(&g_cur[d], 1);
    g_elist[p] = s;
}

// ---------------------------------------------------------------------------
// Weight pre-split: W1s 4x[128k][256n] -> [l][n][k2]; W2s 4x[256k][128n].
// ---------------------------------------------------------------------------
__global__ void wsplit_k(const float* __restrict__ W1s,
                         const float* __restrict__ W2s) {
    int i = blockIdx.x * 256 + threadIdx.x;
    const int T1 = 4 * 64 * 256;
    if (i < T1) {
        int n = i & 255, k2 = (i >> 8) & 63, l = i >> 14;
        float e0 = W1s[l * 32768 + (2 * k2) * 256 + n];
        float e1 = W1s[l * 32768 + (2 * k2 + 1) * 256 + n];
        unsigned wh, wl;
        bfsplit2(e0, e1, wh, wl);
        g_w1h[l * 16384 + n * 64 + k2] = wh;
        g_w1l[l * 16384 + n * 64 + k2] = wl;
    } else {
        int j = i - T1;
        if (j < 4 * 128 * 128) {
            int n = j & 127, k2 = (j >> 7) & 127, l = j >> 14;
            float e0 = W2s[l * 32768 + (2 * k2) * 128 + n];
            float e1 = W2s[l * 32768 + (2 * k2 + 1) * 128 + n];
            unsigned wh, wl;
            bfsplit2(e0, e1, wh, wl);
            g_w2h[l * 16384 + n * 128 + k2] = wh;
            g_w2l[l * 16384 + n * 128 + k2] = wl;
        }
    }
}

// ---------------------------------------------------------------------------
// Gather: agg = X[own] + sum_{j in-nbrs} X[j]; write bf16 hi/lo packed.
// ---------------------------------------------------------------------------
__global__ void gather_k(const float* __restrict__ X, int N) {
    int gw   = (blockIdx.x * blockDim.x + threadIdx.x) >> 5;
    int lane = threadIdx.x & 31;
    if (gw >= N) return;
    int base = g_off[gw];
    int dg   = g_deg[gw];
    float4 acc = *(const float4*)(X + (size_t)gw * 128 + lane * 4);  // own row
    int j = 0;
    for (; j + 2 <= dg; j += 2) {
        int s0 = __ldg(g_elist + base + j);
        int s1 = __ldg(g_elist + base + j + 1);
        float4 a = *(const float4*)(X + (size_t)s0 * 128 + lane * 4);
        float4 b = *(const float4*)(X + (size_t)s1 * 128 + lane * 4);
        acc.x += a.x + b.x; acc.y += a.y + b.y;
        acc.z += a.z + b.z; acc.w += a.w + b.w;
    }
    if (j < dg) {
        int s0 = __ldg(g_elist + base + j);
        float4 a = *(const float4*)(X + (size_t)s0 * 128 + lane * 4);
        acc.x += a.x; acc.y += a.y; acc.z += a.z; acc.w += a.w;
    }
    unsigned wh0, wl0, wh1, wl1;
    bfsplit2(acc.x, acc.y, wh0, wl0);
    bfsplit2(acc.z, acc.w, wh1, wl1);
    size_t o = (size_t)gw * 64 + lane * 2;
    g_axh[o] = wh0; g_axh[o + 1] = wh1;
    g_axl[o] = wl0; g_axl[o + 1] = wl1;
}

// ---------------------------------------------------------------------------
// GEMM common: 128x128 tile, 8 warps (4m x 2n), warp 32x64, m16n8k16, BK=16.
// ---------------------------------------------------------------------------
#define BM 128
#define BN 128
#define BK 16
#define KW 136
#define SAW 20

#define MMA3(ACC, AH, AL, BH0, BH1, BL0, BL1)  \
    do { mma_bf16(ACC, AH, BH0, BH1);          \
         mma_bf16(ACC, AL, BH0, BH1);          \
         mma_bf16(ACC, AH, BL0, BL1); } while (0)

// Operands in [row][k2] layout, stride 12 words (conflict-free).
#define MMA_PHASE12(SAH, SAL, SBH, SBL)                                     \
    {                                                                       \
        unsigned ah[2][4], al[2][4];                                        \
        _Pragma("unroll")                                                   \
        for (int wm = 0; wm < 2; wm++) {                                    \
            int mr = mBase + wm * 16 + lm;                                  \
            ah[wm][0] = (SAH)[mr * 12 + lk];                                \
            ah[wm][1] = (SAH)[(mr + 8) * 12 + lk];                          \
            ah[wm][2] = (SAH)[mr * 12 + lk + 4];                            \
            ah[wm][3] = (SAH)[(mr + 8) * 12 + lk + 4];                      \
            al[wm][0] = (SAL)[mr * 12 + lk];                                \
            al[wm][1] = (SAL)[(mr + 8) * 12 + lk];                          \
            al[wm][2] = (SAL)[mr * 12 + lk + 4];                            \
            al[wm][3] = (SAL)[(mr + 8) * 12 + lk + 4];                      \
        }                                                                   \
        _Pragma("unroll")                                                   \
        for (int wn = 0; wn < 8; wn++) {                                    \
            int nc = nBase + wn * 8 + lm;                                   \
            unsigned bh0 = (SBH)[nc * 12 + lk];                             \
            unsigned bh1 = (SBH)[nc * 12 + lk + 4];                         \
            unsigned bl0 = (SBL)[nc * 12 + lk];                             \
            unsigned bl1 = (SBL)[nc * 12 + lk + 4];                         \
            _Pragma("unroll")                                               \
            for (int wm = 0; wm < 2; wm++)                                  \
                MMA3(acc[wm][wn], ah[wm], al[wm], bh0, bh1, bl0, bl1);      \
        }                                                                   \
    }

// A from KW-stride split arrays, B from stride-12 staging.
#define MMA_PHASE2(AH, AL, SBH, SBL)                                        \
    {                                                                       \
        unsigned ah[2][4], al[2][4];                                        \
        _Pragma("unroll")                                                   \
        for (int wm = 0; wm < 2; wm++) {                                    \
            int mr = mBase + wm * 16 + lm;                                  \
            ah[wm][0] = (AH)[lk * KW + mr];                                 \
            ah[wm][1] = (AH)[lk * KW + mr + 8];                             \
            ah[wm][2] = (AH)[(lk + 4) * KW + mr];                           \
            ah[wm][3] = (AH)[(lk + 4) * KW + mr + 8];                       \
            al[wm][0] = (AL)[lk * KW + mr];                                 \
            al[wm][1] = (AL)[lk * KW + mr + 8];                             \
            al[wm][2] = (AL)[(lk + 4) * KW + mr];                           \
            al[wm][3] = (AL)[(lk + 4) * KW + mr + 8];                       \
        }                                                                   \
        _Pragma("unroll")                                                   \
        for (int wn = 0; wn < 8; wn++) {                                    \
            int nc = nBase + wn * 8 + lm;                                   \
            unsigned bh0 = (SBH)[nc * 12 + lk];                             \
            unsigned bh1 = (SBH)[nc * 12 + lk + 4];                         \
            unsigned bl0 = (SBL)[nc * 12 + lk];                             \
            unsigned bl1 = (SBL)[nc * 12 + lk + 4];                         \
            _Pragma("unroll")                                               \
            for (int wm = 0; wm < 2; wm++)                                  \
                MMA3(acc[wm][wn], ah[wm], al[wm], bh0, bh1, bl0, bl1);      \
        }                                                                   \
    }

// ---------------------------------------------------------------------------
// GEMM1: OUT[:, n0:+128] = presplit(X+agg) @ W1 + bias ; fused stats.
// Fully pre-split operands, 2-stage cp.async double buffer (48KB dynamic).
// Stage layout: [Sah 1536][Sal 1536][Sbh 1536][Sbl 1536] words.
// ---------------------------------------------------------------------------
__global__ void __launch_bounds__(256) gemm1_k(
    const unsigned* __restrict__ whA, const unsigned* __restrict__ wlA,
    const unsigned* __restrict__ whB, const unsigned* __restrict__ wlB,
    const float* __restrict__ bias, float* __restrict__ OUT,
    int N, int ldo) {
    extern __shared__ unsigned dsm[];
    int tid  = threadIdx.x;
    int row0 = blockIdx.y * BM;
    int n0   = blockIdx.x * BN;
    const unsigned* wsh = (n0 < 256) ? whA : whB;
    const unsigned* wsl = (n0 < 256) ? wlA : wlB;
    int nbase = (n0 < 256) ? n0 : (n0 - 256);
    int lane = tid & 31, wid = tid >> 5;
    int lk = lane & 3, lm = lane >> 2;
    int warpM = wid & 3, warpN = wid >> 2;
    int mBase = warpM * 32, nBase = warpN * 64;
    float4 acc[2][8];
    #pragma unroll
    for (int i = 0; i < 2; i++)
        #pragma unroll
        for (int j = 0; j < 8; j++) acc[i][j] = make_float4(0.f,0.f,0.f,0.f);

    auto issue = [&](int t, int st) {
        unsigned* base = dsm + st * 6144;
        int kw = t * 8;
        #pragma unroll
        for (int q = 0; q < 4; q++) {
            int c = q * 256 + tid;
            int arr = c >> 8;
            int r   = c & 255;
            int m   = r >> 1;
            int half = r & 1;
            unsigned* dst = base + arr * 1536 + m * 12 + half * 4;
            const unsigned* src;
            if (arr == 0)      src = g_axh + (size_t)(row0 + m) * 64 + kw + half * 4;
            else if (arr == 1) src = g_axl + (size_t)(row0 + m) * 64 + kw + half * 4;
            else if (arr == 2) src = wsh + (size_t)(nbase + m) * 64 + kw + half * 4;
            else               src = wsl + (size_t)(nbase + m) * 64 + kw + half * 4;
            cp16(dst, src);
        }
        CP_COMMIT();
    };

    issue(0, 0);
    #pragma unroll 1
    for (int t = 0; t < 8; t++) {
        int st = t & 1;
        if (t + 1 < 8) {
            issue(t + 1, st ^ 1);
            CP_WAIT1();
        } else {
            CP_WAIT0();
        }
        __syncthreads();
        unsigned* B0 = dsm + st * 6144;
        MMA_PHASE12(B0, B0 + 1536, B0 + 3072, B0 + 4608)
        __syncthreads();
    }

    float psx[8]={}, psy[8]={}, pqx[8]={}, pqy[8]={};
    #pragma unroll
    for (int wn = 0; wn < 8; wn++) {
        int col = n0 + nBase + wn * 8 + 2 * lk;
        float bx = bias[col], by = bias[col + 1];
        #pragma unroll
        for (int wm = 0; wm < 2; wm++) {
            float4 d = acc[wm][wn];
            int ra = row0 + mBase + wm * 16 + lm;
            int rb = ra + 8;
            float ox = d.x + bx, oy = d.y + by;
            float oz = d.z + bx, ow = d.w + by;
            if (ra < N) {
                *(float2*)(OUT + (size_t)ra * ldo + col) = make_float2(ox, oy);
                psx[wn] += ox; psy[wn] += oy;
                pqx[wn] += ox * ox; pqy[wn] += oy * oy;
            }
            if (rb < N) {
                *(float2*)(OUT + (size_t)rb * ldo + col) = make_float2(oz, ow);
                psx[wn] += oz; psy[wn] += ow;
                pqx[wn] += oz * oz; pqy[wn] += ow * ow;
            }
        }
    }
    #pragma unroll
    for (int wn = 0; wn < 8; wn++) {
        #pragma unroll
        for (int o = 4; o <= 16; o <<= 1) {
            psx[wn] += __shfl_xor_sync(0xffffffffu, psx[wn], o);
            psy[wn] += __shfl_xor_sync(0xffffffffu, psy[wn], o);
            pqx[wn] += __shfl_xor_sync(0xffffffffu, pqx[wn], o);
            pqy[wn] += __shfl_xor_sync(0xffffffffu, pqy[wn], o);
        }
    }
    if (lane < 4) {
        #pragma unroll
        for (int wn = 0; wn < 8; wn++) {
            int col = n0 + nBase + wn * 8 + 2 * lane;
            atomicAdd(&g_colsum[col],     psx[wn]);
            atomicAdd(&g_colsum[col + 1], psy[wn]);
            atomicAdd(&g_colsq[col],      pqx[wn]);
            atomicAdd(&g_colsq[col + 1],  pqy[wn]);
        }
    }
}

__global__ void bnfin_k(const float* __restrict__ gamma,
                        const float* __restrict__ beta, int N) {
    int c = blockIdx.x * blockDim.x + threadIdx.x;
    float invN = 1.0f / (float)N;
    float mu  = g_colsum[c] * invN;
    float var = g_colsq[c] * invN - mu * mu;
    float sc  = gamma[c] * rsqrtf(var + 1e-5f);
    g_scale[c] = sc;
    g_shift[c] = beta[c] - mu * sc;
}

// ---------------------------------------------------------------------------
// GEMM2: OUT[N,128] = BN(HT[:,koff:+256]) [relu] @ W2 + b2.
// A staged + BN/relu/split at runtime; B pre-split, double-buffered staging.
// ---------------------------------------------------------------------------
__global__ void __launch_bounds__(256) gemm2_k(
    const float* __restrict__ HT,
    const unsigned* __restrict__ w2h, const unsigned* __restrict__ w2l,
    const float* __restrict__ bias, float* __restrict__ OUT,
    int N, int ldh, int koff, int relu) {
    __shared__ unsigned Ah[8 * KW], Al[8 * KW];
    __shared__ unsigned Sbh[2 * 1536], Sbl[2 * 1536];
    __shared__ float Sa[128 * SAW];
    int tid  = threadIdx.x;
    int row0 = blockIdx.y * BM;
    int lane = tid & 31, wid = tid >> 5;
    int lk = lane & 3, lm = lane >> 2;
    int warpM = wid & 3, warpN = wid >> 2;
    int mBase = warpM * 32, nBase = warpN * 64;
    float4 acc[2][8];
    #pragma unroll
    for (int i = 0; i < 2; i++)
        #pragma unroll
        for (int j = 0; j < 8; j++) acc[i][j] = make_float4(0.f,0.f,0.f,0.f);

    auto issue = [&](int kk, int st) {
        #pragma unroll
        for (int q = 0; q < 4; q++) {
            int c = q * 256 + tid;
            if (c < 512) {            // A raw fp32 tile
                int m = c >> 2, kq = (c & 3) * 4;
                cp16(Sa + m * SAW + kq,
                     HT + (size_t)(row0 + m) * ldh + koff + kk + kq);
            } else {                  // B pre-split
                int c2 = c - 512;
                int arr = c2 >> 8;
                int r = c2 & 255;
                int n = r >> 1, half = r & 1;
                const unsigned* src = (arr ? w2l : w2h)
                    + (size_t)n * 128 + kk / 2 + half * 4;
                unsigned* dst = (arr ? Sbl : Sbh) + st * 1536 + n * 12 + half * 4;
                cp16(dst, src);
            }
        }
        CP_COMMIT();
    };
    issue(0, 0);

    #pragma unroll 1
    for (int kk = 0; kk < 256; kk += BK) {
        int st = (kk >> 4) & 1;
        CP_WAIT0();
        __syncthreads();
        #pragma unroll
        for (int h = 0; h < 2; h++) {
            int idx = h * 256 + tid;
            int m  = idx & 127;
            int kq = (idx >> 7) * 4;
            float4 a = *(float4*)(Sa + m * SAW + kq);
            float4 sc4 = *(const float4*)(g_scale + koff + kk + kq);
            float4 sh4 = *(const float4*)(g_shift + koff + kk + kq);
            a.x = a.x * sc4.x + sh4.x;
            a.y = a.y * sc4.y + sh4.y;
            a.z = a.z * sc4.z + sh4.z;
            a.w = a.w * sc4.w + sh4.w;
            if (relu) {
                a.x = fmaxf(a.x, 0.f); a.y = fmaxf(a.y, 0.f);
                a.z = fmaxf(a.z, 0.f); a.w = fmaxf(a.w, 0.f);
            }
            unsigned wh0, wl0, wh1, wl1;
            bfsplit2(a.x, a.y, wh0, wl0);
            bfsplit2(a.z, a.w, wh1, wl1);
            int aw = (kq >> 1) * KW + m;
            Ah[aw] = wh0; Al[aw] = wl0;
            Ah[aw + KW] = wh1; Al[aw + KW] = wl1;
        }
        __syncthreads();
        if (kk + BK < 256) issue(kk + BK, st ^ 1);
        MMA_PHASE2(Ah, Al, Sbh + st * 1536, Sbl + st * 1536)
    }

    #pragma unroll
    for (int wn = 0; wn < 8; wn++) {
        int col = nBase + wn * 8 + 2 * lk;
        float bx = bias[col], by = bias[col + 1];
        #pragma unroll
        for (int wm = 0; wm < 2; wm++) {
            float4 d = acc[wm][wn];
            int ra = row0 + mBase + wm * 16 + lm;
            int rb = ra + 8;
            if (ra < N)
                *(float2*)(OUT + (size_t)ra * 128 + col) = make_float2(d.x + bx, d.y + by);
            if (rb < N)
                *(float2*)(OUT + (size_t)rb * 128 + col) = make_float2(d.z + bx, d.w + by);
        }
    }
}

// ---------------------------------------------------------------------------
// z epilogue and small kernels.
// ---------------------------------------------------------------------------
__global__ void z_k(const float* __restrict__ MEAN, const float* __restrict__ LS,
                    const float* __restrict__ NOISE, const int* __restrict__ batch,
                    const float* __restrict__ Wn, const float* __restrict__ Wc,
                    int N) {
    __shared__ float klred[8];
    int lane = threadIdx.x & 31;
    int w    = threadIdx.x >> 5;
    int row  = blockIdx.x * 8 + w;
    float klp = 0.f;
    if (row < N) {
        size_t off = (size_t)row * 128 + lane * 4;
        float4 m4 = *(const float4*)(MEAN + off);
        float4 l4 = *(const float4*)(LS + off);
        float4 n4 = *(const float4*)(NOISE + off);
        float4 e4 = make_float4(expf(l4.x), expf(l4.y), expf(l4.z), expf(l4.w));
        float4 z4 = make_float4(n4.x * e4.x + m4.x, n4.y * e4.y + m4.y,
                                n4.z * e4.z + m4.z, n4.w * e4.w + m4.w);
        float4 wa = *(const float4*)(Wc + lane * 4);
        float4 wb = *(const float4*)(Wc + 128 + lane * 4);
        float4 wn = *(const float4*)(Wn + lane * 4);
        float up = z4.x * wa.x + z4.y * wa.y + z4.z * wa.z + z4.w * wa.w;
        float vp = z4.x * wb.x + z4.y * wb.y + z4.z * wb.z + z4.w * wb.w;
        float sp = z4.x * wn.x + z4.y * wn.y + z4.z * wn.z + z4.w * wn.w;
        klp = (1.f + 2.f * l4.x - m4.x * m4.x - e4.x * e4.x)
            + (1.f + 2.f * l4.y - m4.y * m4.y - e4.y * e4.y)
            + (1.f + 2.f * l4.z - m4.z * m4.z - e4.z * e4.z)
            + (1.f + 2.f * l4.w - m4.w * m4.w - e4.w * e4.w);
        #pragma unroll
        for (int o = 16; o > 0; o >>= 1) {
            up  += __shfl_xor_sync(0xffffffffu, up,  o);
            vp  += __shfl_xor_sync(0xffffffffu, vp,  o);
            sp  += __shfl_xor_sync(0xffffffffu, sp,  o);
            klp += __shfl_xor_sync(0xffffffffu, klp, o);
        }
        if (lane == 0) {
            g_u[row] = up;
            g_v[row] = vp;
            int b = batch[row];
            atomicAdd(&g_pool[b], sp);
            atomicAdd(&g_cnt[b], 1.0f);
        }
    }
    if (lane == 0) klred[w] = (row < N) ? klp : 0.f;
    __syncthreads();
    if (threadIdx.x == 0) {
        float t = 0.f;
        #pragma unroll
        for (int i = 0; i < 8; i++) t += klred[i];
        atomicAdd(&g_acc[0], t);
    }
}

__global__ void num_k(const float* __restrict__ bridge_num,
                      const float* __restrict__ bnp,
                      float* __restrict__ out_np, int G) {
    __shared__ float red[256];
    int g = blockIdx.x * 256 + threadIdx.x;
    float d = 0.f;
    if (g < G) {
        float np = g_pool[g] / g_cnt[g] + bnp[0];
        out_np[g] = np;
        d = fabsf(np - bridge_num[g]);
    }
    red[threadIdx.x] = d;
    __syncthreads();
    for (int s = 128; s > 0; s >>= 1) {
        if (threadIdx.x < s) red[threadIdx.x] += red[threadIdx.x + s];
        __syncthreads();
    }
    if (threadIdx.x == 0) atomicAdd(&g_acc[1], red[0]);
}

__global__ void apred_k(const int* __restrict__ bidx,
                        const float* __restrict__ bcp,
                        float* __restrict__ out, int P) {
    int p = blockIdx.x * 256 + threadIdx.x;
    if (p >= P) return;
    int i = __ldg(bidx + p);
    int j = __ldg(bidx + P + p);
    float logit = g_u[i] + g_v[j] + bcp[0];
    out[p] = 1.0f / (1.0f + expf(-logit));
}

__global__ void fin_k(float* __restrict__ out, int P, int N, int G) {
    out[P]     = 0.5f * g_acc[0] / ((float)N * (float)N);
    out[P + 1] = g_acc[1] / (float)G;
}

// ---------------------------------------------------------------------------
// Launcher
// ---------------------------------------------------------------------------
extern "C" void kernel_launch(void* const* d_in, const int* in_sizes, int n_in,
                              void* d_out, int out_size) {
    const float* x          = (const float*)d_in[0];
    const int*   ei         = (const int*)  d_in[1];
    const int*   batch      = (const int*)  d_in[2];
    const float* bridge_num = (const float*)d_in[3];
    const int*   bidx       = (const int*)  d_in[4];
    const float* noise      = (const float*)d_in[5];
    const float* W1s        = (const float*)d_in[6];
    const float* b1s        = (const float*)d_in[7];
    const float* gammas     = (const float*)d_in[8];
    const float* betas      = (const float*)d_in[9];
    const float* W2s        = (const float*)d_in[10];
    const float* b2s        = (const float*)d_in[11];
    const float* Wn         = (const float*)d_in[12];
    const float* bnp        = (const float*)d_in[13];
    const float* Wc         = (const float*)d_in[14];
    const float* bcp        = (const float*)d_in[15];
    float* out = (float*)d_out;

    int N = in_sizes[0] / 128;
    int E = in_sizes[1] / 2;
    int G = in_sizes[3];
    int P = in_sizes[4] / 2;

    float *ht, *h1, *h2, *mean, *ls, *colsum, *colsq, *pool, *cnt, *acc;
    int *deg;
    unsigned *w1h, *w1l, *w2h, *w2l;
    cudaGetSymbolAddress((void**)&ht,     g_ht);
    cudaGetSymbolAddress((void**)&h1,     g_h1);
    cudaGetSymbolAddress((void**)&h2,     g_h2);
    cudaGetSymbolAddress((void**)&mean,   g_mean);
    cudaGetSymbolAddress((void**)&ls,     g_ls);
    cudaGetSymbolAddress((void**)&colsum, g_colsum);
    cudaGetSymbolAddress((void**)&colsq,  g_colsq);
    cudaGetSymbolAddress((void**)&pool,   g_pool);
    cudaGetSymbolAddress((void**)&cnt,    g_cnt);
    cudaGetSymbolAddress((void**)&acc,    g_acc);
    cudaGetSymbolAddress((void**)&deg,    g_deg);
    cudaGetSymbolAddress((void**)&w1h,    g_w1h);
    cudaGetSymbolAddress((void**)&w1l,    g_w1l);
    cudaGetSymbolAddress((void**)&w2h,    g_w2h);
    cudaGetSymbolAddress((void**)&w2l,    g_w2l);

    int rb = (N + BM - 1) / BM;
    int nb256 = (N + 255) / 256;
    int gather_blocks = (N * 32 + 255) / 256;
    const int DSM = 49152;

    // ---- build CSR + pre-split weights (once) ----
    cudaMemsetAsync(deg, 0, N * sizeof(int));
    hist_k<<<(E + 255) / 256, 256>>>(ei, E, N);
    wsplit_k<<<512, 256>>>(W1s, W2s);
    scan1_k<<<nb256, 256>>>(N);
    scan2_k<<<1, 512>>>(nb256);
    scan3_k<<<nb256, 256>>>(N);
    fill_k<<<(E + 255) / 256, 256>>>(ei, E);

    // ---- layer 0 ----
    gather_k<<<gather_blocks, 256>>>(x, N);
    cudaMemsetAsync(colsum, 0, 512 * sizeof(float));
    cudaMemsetAsync(colsq,  0, 512 * sizeof(float));
    gemm1_k<<<dim3(2, rb), 256, DSM>>>(w1h, w1l, w1h, w1l, b1s, ht, N, 256);
    bnfin_k<<<1, 256>>>(gammas, betas, N);
    gemm2_k<<<dim3(1, rb), 256>>>(ht, w2h, w2l, b2s, h1, N, 256, 0, 1);

    // ---- layer 1 ----
    gather_k<<<gather_blocks, 256>>>(h1, N);
    cudaMemsetAsync(colsum, 0, 512 * sizeof(float));
    cudaMemsetAsync(colsq,  0, 512 * sizeof(float));
    gemm1_k<<<dim3(2, rb), 256, DSM>>>(w1h + 16384, w1l + 16384,
                                       w1h + 16384, w1l + 16384, b1s + 256, ht, N, 256);
    bnfin_k<<<1, 256>>>(gammas + 256, betas + 256, N);
    gemm2_k<<<dim3(1, rb), 256>>>(ht, w2h + 16384, w2l + 16384, b2s + 128, h2, N, 256, 0, 1);

    // ---- layers 2+3 combined ----
    gather_k<<<gather_blocks, 256>>>(h2, N);
    cudaMemsetAsync(colsum, 0, 512 * sizeof(float));
    cudaMemsetAsync(colsq,  0, 512 * sizeof(float));
    gemm1_k<<<dim3(4, rb), 256, DSM>>>(w1h + 2 * 16384, w1l + 2 * 16384,
                                       w1h + 3 * 16384, w1l + 3 * 16384,
                                       b1s + 512, ht, N, 512);
    bnfin_k<<<1, 512>>>(gammas + 512, betas + 512, N);
    gemm2_k<<<dim3(1, rb), 256>>>(ht, w2h + 2 * 16384, w2l + 2 * 16384,
                                  b2s + 256, mean, N, 512, 0,   0);
    gemm2_k<<<dim3(1, rb), 256>>>(ht, w2h + 3 * 16384, w2l + 3 * 16384,
                                  b2s + 384, ls,   N, 512, 256, 0);

    // ---- epilogue ----
    cudaMemsetAsync(pool, 0, G * sizeof(float));
    cudaMemsetAsync(cnt,  0, G * sizeof(float));
    cudaMemsetAsync(acc,  0, 2 * sizeof(float));
    z_k<<<(N + 7) / 8, 256>>>(mean, ls, noise, batch, Wn, Wc, N);
    num_k<<<(G + 255) / 256, 256>>>(bridge_num, bnp, out + P + 2, G);
    apred_k<<<(P + 255) / 256, 256>>>(bidx, bcp, out, P);
    fin_k<<<1, 1>>>(out, P, N, G);
}